// round 13
// baseline (speedup 1.0000x reference)
#include <cuda_runtime.h>
#include <cuda_bf16.h>
#include <cstdint>
#include <cstddef>

#define TT   2048
#define EE   300
#define HH   512

__device__ float g_gx[(size_t)4 * TT * 2048];   // [dir*2+sent][t][4H]
__device__ float g_h[2][2][2][HH];              // [parity][dir][sent][H]
__device__ int   g_tile_cnt[4][32];             // [dir*2+sent][stored t-tile] -> 32 when ready

__device__ __forceinline__ float sigf(float x) { return 1.f / (1.f + __expf(-x)); }
__device__ __forceinline__ float tanh_fast(float x) {
    float e = __expf(2.f * x);
    return 1.f - __fdividef(2.f, e + 1.f);
}

__device__ __forceinline__ uint32_t smem_u32(const void* p) {
    uint32_t a;
    asm("{ .reg .u64 t; cvta.to.shared.u64 t, %1; cvt.u32.u64 %0, t; }" : "=r"(a) : "l"(p));
    return a;
}
__device__ __forceinline__ uint32_t mapa_u32(uint32_t addr, uint32_t rank) {
    uint32_t r;
    asm("mapa.shared::cluster.u32 %0, %1, %2;" : "=r"(r) : "r"(addr), "r"(rank));
    return r;
}
__device__ __forceinline__ void fma2(unsigned long long& acc,
                                     unsigned long long a, unsigned long long b) {
    asm("fma.rn.f32x2 %0, %1, %2, %0;" : "+l"(acc) : "l"(a), "l"(b));
}
__device__ __forceinline__ float acc2_sum(unsigned long long acc) {
    float lo, hi;
    asm("mov.b64 {%0, %1}, %2;" : "=f"(lo), "=f"(hi) : "l"(acc));
    return lo + hi;
}
__device__ __forceinline__ unsigned long long pack2(float a, float b) {
    unsigned long long r;
    asm("mov.b64 %0, {%1, %2};" : "=l"(r) : "f"(a), "f"(b));
    return r;
}
__device__ __forceinline__ void unpack2(unsigned long long v, float& a, float& b) {
    asm("mov.b64 {%0, %1}, %2;" : "=f"(a), "=f"(b) : "l"(v));
}
__device__ __forceinline__ void add2(unsigned long long& acc, unsigned long long v) {
    asm("add.rn.f32x2 %0, %0, %1;" : "+l"(acc) : "l"(v));
}
__device__ __forceinline__ int ld_acq_gpu(const int* p) {
    int v;
    asm volatile("ld.acquire.gpu.global.b32 %0, [%1];" : "=r"(v) : "l"(p) : "memory");
    return v;
}

// Reduce 4 packed (A,B) row-sums across the warp.
// Result: lane0 holds row0's sum, lane8 row1, lane16 row2, lane24 row3 (packed A,B).
__device__ __forceinline__ unsigned long long reduce4_val(
    unsigned long long v0, unsigned long long v1,
    unsigned long long v2, unsigned long long v3, int lane)
{
    add2(v0, __shfl_xor_sync(0xffffffffu, v0, 16));
    add2(v1, __shfl_xor_sync(0xffffffffu, v1, 16));
    add2(v2, __shfl_xor_sync(0xffffffffu, v2, 16));
    add2(v3, __shfl_xor_sync(0xffffffffu, v3, 16));
    add2(v0, __shfl_xor_sync(0xffffffffu, v0, 8));
    add2(v1, __shfl_xor_sync(0xffffffffu, v1, 8));
    add2(v2, __shfl_xor_sync(0xffffffffu, v2, 8));
    add2(v3, __shfl_xor_sync(0xffffffffu, v3, 8));
    const int j = lane >> 3;
    unsigned long long val = v0;
    if (j == 1) val = v1;
    if (j == 2) val = v2;
    if (j == 3) val = v3;
    add2(val, __shfl_xor_sync(0xffffffffu, val, 4));
    add2(val, __shfl_xor_sync(0xffffffffu, val, 2));
    add2(val, __shfl_xor_sync(0xffffffffu, val, 1));
    return val;
}

#define MBAR_INIT(addr, cnt) \
    asm volatile("mbarrier.init.shared.b64 [%0], %1;" :: "r"(addr), "r"(cnt) : "memory")
#define MBAR_EXPECT_TX(addr, tx) \
    asm volatile("mbarrier.arrive.expect_tx.shared.b64 _, [%0], %1;" :: "r"(addr), "r"(tx) : "memory")
#define MBAR_WAIT_PARITY(addr, ph) do {                                              \
    uint32_t _m = (addr), _p = (ph), _d;                                             \
    asm volatile("{\n\t.reg .pred p;\n\t"                                            \
        "mbarrier.try_wait.parity.acquire.cta.shared::cta.b64 p, [%1], %2;\n\t"      \
        "selp.b32 %0, 1, 0, p;\n\t}"                                                 \
        : "=r"(_d) : "r"(_m), "r"(_p) : "memory");                                   \
    if (!_d) {                                                                        \
        asm volatile("{\n\t.reg .pred P1;\n\t"                                       \
            "WL_%=:\n\t"                                                              \
            "mbarrier.try_wait.parity.acquire.cta.shared::cta.b64 P1, [%0], %1, 0x989680;\n\t" \
            "@P1 bra.uni WD_%=;\n\t"                                                  \
            "bra.uni WL_%=;\n\t"                                                      \
            "WD_%=:\n\t}"                                                             \
            :: "r"(_m), "r"(_p) : "memory");                                          \
    }                                                                                 \
} while (0)

// ---------------- init: zero tile counters -----------------------------------------
__global__ void init_kernel() {
    int i = threadIdx.x;
    if (i < 128) ((int*)g_tile_cnt)[i] = 0;
}

// ---------------- standalone gx GEMM (fallback path), 256 threads ------------------
__global__ void gemm_gx_kernel(const int* __restrict__ sA, const int* __restrict__ sB,
                               const float* __restrict__ emb,
                               const float* __restrict__ w_ih,
                               const float* __restrict__ b_ih,
                               const float* __restrict__ b_hh)
{
    const int t0 = blockIdx.x * 64;
    const int r0 = blockIdx.y * 64;
    const int s  = blockIdx.z;
    const int* sent = s ? sB : sA;
    const int d = r0 >> 11;

    __shared__ float As[32][65];
    __shared__ float Bs[32][65];
    __shared__ int   toks[64];

    const int tid = threadIdx.x;
    const int ty = tid >> 4, tx = tid & 15;

    if (tid < 64) toks[tid] = sent[t0 + tid];
    __syncthreads();

    float acc[4][4] = {};

    for (int k0 = 0; k0 < EE; k0 += 32) {
#pragma unroll
        for (int m = 0; m < 8; ++m) {
            int idx = tid + m * 256;
            int tt = idx >> 5, kk = idx & 31;
            int k = k0 + kk;
            As[kk][tt] = (k < EE) ? emb[(size_t)toks[tt] * EE + k] : 0.f;
        }
#pragma unroll
        for (int m = 0; m < 8; ++m) {
            int idx = tid + m * 256;
            int rr = idx >> 5, kk = idx & 31;
            int k = k0 + kk;
            Bs[kk][rr] = (k < EE) ? w_ih[(size_t)(r0 + rr) * EE + k] : 0.f;
        }
        __syncthreads();
#pragma unroll
        for (int kk = 0; kk < 32; ++kk) {
            float a0 = As[kk][ty * 4 + 0], a1 = As[kk][ty * 4 + 1];
            float a2 = As[kk][ty * 4 + 2], a3 = As[kk][ty * 4 + 3];
            float b0 = Bs[kk][tx + 16 * 0], b1 = Bs[kk][tx + 16 * 1];
            float b2 = Bs[kk][tx + 16 * 2], b3 = Bs[kk][tx + 16 * 3];
            acc[0][0] += a0 * b0; acc[0][1] += a0 * b1; acc[0][2] += a0 * b2; acc[0][3] += a0 * b3;
            acc[1][0] += a1 * b0; acc[1][1] += a1 * b1; acc[1][2] += a1 * b2; acc[1][3] += a1 * b3;
            acc[2][0] += a2 * b0; acc[2][1] += a2 * b1; acc[2][2] += a2 * b2; acc[2][3] += a2 * b3;
            acc[3][0] += a3 * b0; acc[3][1] += a3 * b1; acc[3][2] += a3 * b2; acc[3][3] += a3 * b3;
        }
        __syncthreads();
    }

#pragma unroll
    for (int i = 0; i < 4; ++i) {
        int t = t0 + ty * 4 + i;
        int tstore = d ? (TT - 1 - t) : t;
        size_t rowbase = (((size_t)(d * 2 + s)) * TT + tstore) * 2048;
#pragma unroll
        for (int j = 0; j < 4; ++j) {
            int r = r0 + tx + 16 * j;
            g_gx[rowbase + (r & 2047)] = acc[i][j] + b_ih[r] + b_hh[r];
        }
    }
}

// ---------------- worker body: gx GEMM tiles with 512 threads ----------------------
__device__ void worker_body(int widx, int nwork, char* smem_raw,
                            const int* sA, const int* sB,
                            const float* emb, const float* w_ih,
                            const float* b_ih, const float* b_hh)
{
    float* As = reinterpret_cast<float*>(smem_raw);              // [32][65]
    float* Bs = As + 32 * 65;                                    // [32][65]
    int*   toks = reinterpret_cast<int*>(Bs + 32 * 65);          // [64]

    const int tid = threadIdx.x;
    const int ty = tid >> 4;          // 0..31 (2 t-rows each)
    const int tx = tid & 15;

    for (int i = widx; i < 4096; i += nwork) {
        const int stt = i >> 7;
        const int sub = i & 127;
        const int y   = sub >> 1;
        const int s   = sub & 1;
        const int d   = y >> 5;
        const int t0  = (d ? (31 - stt) : stt) << 6;
        const int r0  = y << 6;
        const int* sent = s ? sB : sA;

        if (tid < 64) toks[tid] = sent[t0 + tid];
        __syncthreads();

        float acc[2][4] = {};

        for (int k0 = 0; k0 < EE; k0 += 32) {
#pragma unroll
            for (int m = 0; m < 4; ++m) {
                int idx = tid + m * 512;
                int tt = idx >> 5, kk = idx & 31;
                int k = k0 + kk;
                As[kk * 65 + tt] = (k < EE) ? emb[(size_t)toks[tt] * EE + k] : 0.f;
            }
#pragma unroll
            for (int m = 0; m < 4; ++m) {
                int idx = tid + m * 512;
                int rr = idx >> 5, kk = idx & 31;
                int k = k0 + kk;
                Bs[kk * 65 + rr] = (k < EE) ? w_ih[(size_t)(r0 + rr) * EE + k] : 0.f;
            }
            __syncthreads();
#pragma unroll
            for (int kk = 0; kk < 32; ++kk) {
                float a0 = As[kk * 65 + ty * 2 + 0];
                float a1 = As[kk * 65 + ty * 2 + 1];
                float b0 = Bs[kk * 65 + tx + 16 * 0], b1 = Bs[kk * 65 + tx + 16 * 1];
                float b2 = Bs[kk * 65 + tx + 16 * 2], b3 = Bs[kk * 65 + tx + 16 * 3];
                acc[0][0] += a0 * b0; acc[0][1] += a0 * b1; acc[0][2] += a0 * b2; acc[0][3] += a0 * b3;
                acc[1][0] += a1 * b0; acc[1][1] += a1 * b1; acc[1][2] += a1 * b2; acc[1][3] += a1 * b3;
            }
            __syncthreads();
        }

#pragma unroll
        for (int ii = 0; ii < 2; ++ii) {
            int t = t0 + ty * 2 + ii;
            int tstore = d ? (TT - 1 - t) : t;
            size_t rowbase = (((size_t)(d * 2 + s)) * TT + tstore) * 2048;
#pragma unroll
            for (int j = 0; j < 4; ++j) {
                int r = r0 + tx + 16 * j;
                g_gx[rowbase + (r & 2047)] = acc[ii][j] + b_ih[r] + b_hh[r];
            }
        }
        __syncthreads();
        if (tid == 0) {
            __threadfence();
            atomicAdd(&g_tile_cnt[d * 2 + s][stt], 1);
        }
        __syncthreads();
    }
}

// ---------------- fused kernel: LSTM clusters + GEMM worker clusters ---------------
// LSTM: warp w owns ALL 4 gates of its NB=UPC/16 units -> pointwise happens inside
// the matvec warp right after reduction (no gates smem, no barrier-serialized tail).
template <int CSZ>
__global__ void __launch_bounds__(512, 1)
lstm_fused_kernel(const float* __restrict__ w_hh,
                  const int* __restrict__ sA, const int* __restrict__ sB,
                  const float* __restrict__ emb, const float* __restrict__ w_ih,
                  const float* __restrict__ b_ih, const float* __restrict__ b_hh,
                  int wait_tiles, int n_worker_ctas)
{
    extern __shared__ float smf[];

    if (blockIdx.x >= 2 * CSZ) {
        worker_body(blockIdx.x - 2 * CSZ, n_worker_ctas, reinterpret_cast<char*>(smf),
                    sA, sB, emb, w_ih, b_ih, b_hh);
        return;
    }

    constexpr int NT   = 512;
    constexpr int NW   = 16;
    constexpr int UPC  = HH / CSZ;
    constexpr int NB   = UPC / NW;          // units per warp (2 for CSZ=16)
    constexpr int RPW  = 4 * NB;            // rows per warp
    constexpr int REG_ROWS  = 2;
    constexpr int SMEM_ROWS = 6;
    constexpr int CHUNK = UPC * 4;
    constexpr uint32_t TX_TOTAL = 2 * HH * 4;

    float* w_sm  = smf;                                     // NW*SMEM_ROWS*HH
    float* h_s   = w_sm + NW * SMEM_ROWS * HH;              // [2][2*HH]
    float* stage = h_s + 4 * HH;                            // [2][2][UPC]
    unsigned long long* s_bar = reinterpret_cast<unsigned long long*>(stage + 4 * UPC);

    const int tid  = threadIdx.x;
    const int lane = tid & 31;
    const int wid  = tid >> 5;
    const int dir  = blockIdx.x / CSZ;
    const int rank = blockIdx.x % CSZ;
    const int ku   = rank * UPC;

    for (int i = tid; i < 2 * HH; i += NT) h_s[i] = 0.f;
    if (tid == 0) {
        MBAR_INIT(smem_u32(&s_bar[0]), 1);
        MBAR_INIT(smem_u32(&s_bar[1]), 1);
    }

    // row j (0..RPW-1) of this warp: gate = j&3, local unit = wid*NB + (j>>2)
    const float* wbase = w_hh + (size_t)dir * 2048 * HH;
    auto rowptr = [&](int j) {
        return wbase + ((size_t)(j & 3) * HH + ku + wid * NB + (j >> 2)) * HH;
    };

    // one-time: SMEM rows (j = REG_ROWS .. REG_ROWS+SMEM_ROWS-1)
    for (int j = 0; j < SMEM_ROWS; ++j) {
        const float4* src = reinterpret_cast<const float4*>(rowptr(REG_ROWS + j));
        float4* dst = reinterpret_cast<float4*>(w_sm + (size_t)(wid * SMEM_ROWS + j) * HH);
        for (int i = lane; i < HH / 4; i += 32) dst[i] = src[i];
    }

    // one-time: register rows (j = 0 .. REG_ROWS-1)
    ulonglong2 wreg[REG_ROWS][4];
#pragma unroll
    for (int j = 0; j < REG_ROWS; ++j) {
        const ulonglong2* wr = reinterpret_cast<const ulonglong2*>(rowptr(j));
#pragma unroll
        for (int i = 0; i < 4; ++i) wreg[j][i] = wr[lane + 32 * i];
    }

    __syncthreads();
    asm volatile("barrier.cluster.arrive.aligned;" ::: "memory");
    asm volatile("barrier.cluster.wait.aligned;"   ::: "memory");

    const uint32_t bar_a[2]  = { smem_u32(&s_bar[0]), smem_u32(&s_bar[1]) };
    const uint32_t hbuf_a[2] = { smem_u32(h_s), smem_u32(h_s + 2 * HH) };
    const uint32_t stage_a   = smem_u32(stage);

    const ulonglong2* wsm2 = reinterpret_cast<const ulonglong2*>(
        w_sm + (size_t)(wid * SMEM_ROWS) * HH);

    // per-lane cell state: lane 0 = sentence A, lane 1 = sentence B, NB units each
    float c_st[NB];
#pragma unroll
    for (int i = 0; i < NB; ++i) c_st[i] = 0.f;

    for (int t = 0; t < TT; ++t) {
        const int rb = t & 1;
        const int wb = (t + 1) & 1;
        const int bi = t & 1;
        const int ph = (t >> 1) & 1;
        const int sb = t & 1;

        // wait for this 64-step gx tile from the workers (acquire)
        if (wait_tiles && (t & 63) == 0) {
            const int tt = t >> 6;
            const int* c0 = &g_tile_cnt[dir * 2 + 0][tt];
            const int* c1 = &g_tile_cnt[dir * 2 + 1][tt];
            while (ld_acq_gpu(c0) < 32) {}
            while (ld_acq_gpu(c1) < 32) {}
        }

        if (tid == 0) MBAR_EXPECT_TX(bar_a[bi], TX_TOTAL);

        // lanes 0/1: load gx for this warp's units (sentence = lane)
        float gxv[NB][4];
        if (lane < 2) {
            const float* px = g_gx + ((size_t)(dir * 2 + lane) * TT + t) * 2048
                              + ku + wid * NB;
#pragma unroll
            for (int b = 0; b < NB; ++b)
#pragma unroll
                for (int g = 0; g < 4; ++g) gxv[b][g] = __ldg(px + g * HH + b);
        }

        // h into registers
        const ulonglong2* hA2 = reinterpret_cast<const ulonglong2*>(h_s + rb * 2 * HH);
        const ulonglong2* hB2 = reinterpret_cast<const ulonglong2*>(h_s + rb * 2 * HH + HH);
        ulonglong2 ha[4], hb[4];
#pragma unroll
        for (int i = 0; i < 4; ++i) {
            ha[i] = hA2[lane + 32 * i];
            hb[i] = hB2[lane + 32 * i];
        }

        // ---- per-unit batch: matvec 4 gate-rows, reduce, pointwise in-warp ----
#pragma unroll
        for (int b = 0; b < NB; ++b) {
            unsigned long long aA[4] = {0,0,0,0}, aB[4] = {0,0,0,0};
#pragma unroll
            for (int r = 0; r < 4; ++r) {
                const int j = 4 * b + r;
                ulonglong2 wv0, wv1, wv2, wv3;
                if (j < REG_ROWS) {
                    wv0 = wreg[j][0]; wv1 = wreg[j][1]; wv2 = wreg[j][2]; wv3 = wreg[j][3];
                } else if (j < REG_ROWS + SMEM_ROWS) {
                    const ulonglong2* wr = wsm2 + (size_t)(j - REG_ROWS) * (HH / 4);
                    wv0 = wr[lane]; wv1 = wr[lane + 32]; wv2 = wr[lane + 64]; wv3 = wr[lane + 96];
                } else {
                    const ulonglong2* wr = reinterpret_cast<const ulonglong2*>(rowptr(j));
                    wv0 = wr[lane]; wv1 = wr[lane + 32]; wv2 = wr[lane + 64]; wv3 = wr[lane + 96];
                }
                fma2(aA[r], wv0.x, ha[0].x); fma2(aA[r], wv0.y, ha[0].y);
                fma2(aA[r], wv1.x, ha[1].x); fma2(aA[r], wv1.y, ha[1].y);
                fma2(aA[r], wv2.x, ha[2].x); fma2(aA[r], wv2.y, ha[2].y);
                fma2(aA[r], wv3.x, ha[3].x); fma2(aA[r], wv3.y, ha[3].y);
                fma2(aB[r], wv0.x, hb[0].x); fma2(aB[r], wv0.y, hb[0].y);
                fma2(aB[r], wv1.x, hb[1].x); fma2(aB[r], wv1.y, hb[1].y);
                fma2(aB[r], wv2.x, hb[2].x); fma2(aB[r], wv2.y, hb[2].y);
                fma2(aB[r], wv3.x, hb[3].x); fma2(aB[r], wv3.y, hb[3].y);
            }
            unsigned long long val = reduce4_val(
                pack2(acc2_sum(aA[0]), acc2_sum(aB[0])),
                pack2(acc2_sum(aA[1]), acc2_sum(aB[1])),
                pack2(acc2_sum(aA[2]), acc2_sum(aB[2])),
                pack2(acc2_sum(aA[3]), acc2_sum(aB[3])), lane);

            // broadcast the 4 gate sums (packed A,B) to all lanes
            unsigned long long vg0 = __shfl_sync(0xffffffffu, val, 0);
            unsigned long long vg1 = __shfl_sync(0xffffffffu, val, 8);
            unsigned long long vg2 = __shfl_sync(0xffffffffu, val, 16);
            unsigned long long vg3 = __shfl_sync(0xffffffffu, val, 24);

            // lanes 0/1 do the pointwise update for sentence A/B of this unit
            if (lane < 2) {
                float a0, b0, a1, b1, a2, b2, a3, b3;
                unpack2(vg0, a0, b0);
                unpack2(vg1, a1, b1);
                unpack2(vg2, a2, b2);
                unpack2(vg3, a3, b3);
                float gi = (lane == 0 ? a0 : b0) + gxv[b][0];
                float gf = (lane == 0 ? a1 : b1) + gxv[b][1];
                float gg = (lane == 0 ? a2 : b2) + gxv[b][2];
                float go = (lane == 0 ? a3 : b3) + gxv[b][3];
                c_st[b] = sigf(gf) * c_st[b] + sigf(gi) * tanh_fast(gg);
                float hv = sigf(go) * tanh_fast(c_st[b]);
                int uu = wid * NB + b;
                stage[sb * 2 * UPC + lane * UPC + uu] = hv;
                if (t == TT - 1) g_h[0][dir][lane][ku + uu] = hv;
            }
        }

        __syncthreads();   // all stage writes complete (only CTA barrier per step)

        // ---- warp 0: ship both sentence slices to all cluster CTAs ----
        if (wid == 0) {
            asm volatile("fence.proxy.async.shared::cta;" ::: "memory");
            if (lane < 2 * CSZ) {
                const uint32_t peer = (uint32_t)(lane >> 1);
                const uint32_t c    = (uint32_t)(lane & 1);
                uint32_t src  = stage_a + (sb * 2 * UPC + c * UPC) * 4;
                uint32_t ldst = hbuf_a[wb] + (c * HH + ku) * 4;
                uint32_t rdst = mapa_u32(ldst, peer);
                uint32_t rbar = mapa_u32(bar_a[bi], peer);
                asm volatile(
                    "cp.async.bulk.shared::cluster.shared::cta.mbarrier::complete_tx::bytes "
                    "[%0], [%1], %2, [%3];"
                    :: "r"(rdst), "r"(src), "n"(CHUNK), "r"(rbar) : "memory");
            }
        }

        MBAR_WAIT_PARITY(bar_a[bi], (uint32_t)ph);
    }
}

// ---------------- phase 3: head ------------------------------------------------------
__global__ void head_kernel(const float* __restrict__ bi_w, const float* __restrict__ bi_b,
                            const float* __restrict__ blA, const float* __restrict__ blB,
                            const float* __restrict__ bl_b,
                            const float* __restrict__ out_w, const float* __restrict__ out_b,
                            float* __restrict__ out)
{
    __shared__ float hA[HH], hB[HH];
    __shared__ float red[16];
    const int j = threadIdx.x;
    const float w0 = bi_w[0], w1 = bi_w[1], bb = bi_b[0];

    hA[j] = w0 * g_h[0][0][0][j] + w1 * g_h[0][1][0][j] + bb;
    hB[j] = w0 * g_h[0][0][1][j] + w1 * g_h[0][1][1][j] + bb;
    __syncthreads();

    float acc = bl_b[j];
#pragma unroll 4
    for (int i = 0; i < HH; ++i)
        acc += hA[i] * blA[(size_t)i * HH + j] + hB[i] * blB[(size_t)i * HH + j];

    float v = tanhf(acc) * out_w[j];
#pragma unroll
    for (int off = 16; off; off >>= 1) v += __shfl_xor_sync(0xffffffffu, v, off);
    if ((j & 31) == 0) red[j >> 5] = v;
    __syncthreads();
    if (j < 16) {
        float r = red[j];
#pragma unroll
        for (int off = 8; off; off >>= 1) r += __shfl_xor_sync(0x0000ffffu, r, off);
        if (j == 0) out[0] = 1.f / (1.f + expf(-(r + out_b[0])));
    }
}

// ---------------- launch --------------------------------------------------------------
extern "C" void kernel_launch(void* const* d_in, const int* in_sizes, int n_in,
                              void* d_out, int out_size)
{
    (void)in_sizes; (void)n_in; (void)out_size;
    const int*   sentA = (const int*)d_in[0];
    const int*   sentB = (const int*)d_in[1];
    const float* emb   = (const float*)d_in[3];
    const float* w_ih  = (const float*)d_in[4];
    const float* w_hh  = (const float*)d_in[5];
    const float* b_ih  = (const float*)d_in[6];
    const float* b_hh  = (const float*)d_in[7];
    const float* bi_w  = (const float*)d_in[8];
    const float* bi_b  = (const float*)d_in[9];
    const float* blA   = (const float*)d_in[10];
    const float* blB   = (const float*)d_in[11];
    const float* bl_b  = (const float*)d_in[12];
    const float* out_w = (const float*)d_in[13];
    const float* out_b = (const float*)d_in[14];
    float* out = (float*)d_out;

    auto smem_for = [](int csz) {
        int upc = HH / csz;
        return (int)((16 * 6 * HH + 4 * HH + 4 * upc) * sizeof(float)) + 16;
    };
    const int smem16 = smem_for(16);
    const int smem8  = smem_for(8);

    cudaFuncSetAttribute(lstm_fused_kernel<16>,
                         cudaFuncAttributeNonPortableClusterSizeAllowed, 1);
    cudaFuncSetAttribute(lstm_fused_kernel<16>,
                         cudaFuncAttributeMaxDynamicSharedMemorySize, smem16);
    cudaFuncSetAttribute(lstm_fused_kernel<8>,
                         cudaFuncAttributeMaxDynamicSharedMemorySize, smem8);

    cudaLaunchConfig_t cfg = {};
    cfg.blockDim = dim3(512, 1, 1);
    cfg.stream = 0;
    cudaLaunchAttribute attr[1];
    attr[0].id = cudaLaunchAttributeClusterDimension;
    cfg.attrs = attr;
    cfg.numAttrs = 1;

    cfg.gridDim = dim3(2 * 16, 1, 1);
    cfg.dynamicSmemBytes = smem16;
    attr[0].val.clusterDim.x = 16; attr[0].val.clusterDim.y = 1; attr[0].val.clusterDim.z = 1;

    int ncl = 0;
    cudaError_t e = cudaOccupancyMaxActiveClusters(&ncl, lstm_fused_kernel<16>, &cfg);
    if (e == cudaSuccess && ncl >= 3) {
        int use = ncl < 9 ? ncl : 9;
        int nworkers = (use - 2) * 16;
        cfg.gridDim = dim3(use * 16, 1, 1);
        init_kernel<<<1, 128>>>();
        cudaLaunchKernelEx(&cfg, lstm_fused_kernel<16>,
                           w_hh, sentA, sentB, emb, w_ih, b_ih, b_hh, 1, nworkers);
    } else {
        (void)cudaGetLastError();
        gemm_gx_kernel<<<dim3(32, 64, 2), 256>>>(sentA, sentB, emb, w_ih, b_ih, b_hh);
        if (e == cudaSuccess && ncl >= 1) {
            cfg.gridDim = dim3(2 * 16, 1, 1);
            cudaLaunchKernelEx(&cfg, lstm_fused_kernel<16>,
                               w_hh, sentA, sentB, emb, w_ih, b_ih, b_hh, 0, 0);
        } else {
            (void)cudaGetLastError();
            cfg.gridDim = dim3(2 * 8, 1, 1);
            cfg.dynamicSmemBytes = smem8;
            attr[0].val.clusterDim.x = 8;
            cudaLaunchKernelEx(&cfg, lstm_fused_kernel<8>,
                               w_hh, sentA, sentB, emb, w_ih, b_ih, b_hh, 0, 0);
        }
    }

    head_kernel<<<1, 512>>>(bi_w, bi_b, blA, blB, bl_b, out_w, out_b, out);
}

// round 14
// speedup vs baseline: 1.3042x; 1.3042x over previous
#include <cuda_runtime.h>
#include <cuda_bf16.h>
#include <cstdint>
#include <cstddef>

#define TT   2048
#define EE   300
#define HH   512

__device__ float g_gx[(size_t)4 * TT * 2048];   // [dir*2+sent][t][4H]
__device__ float g_h[2][2][2][HH];              // [parity][dir][sent][H]
__device__ int   g_tile_cnt[4][32];             // [dir*2+sent][stored t-tile] -> 32 when ready

__device__ __forceinline__ float sigf(float x) { return 1.f / (1.f + __expf(-x)); }
__device__ __forceinline__ float tanh_fast(float x) {
    float e = __expf(2.f * x);
    return 1.f - __fdividef(2.f, e + 1.f);
}

__device__ __forceinline__ uint32_t smem_u32(const void* p) {
    uint32_t a;
    asm("{ .reg .u64 t; cvta.to.shared.u64 t, %1; cvt.u32.u64 %0, t; }" : "=r"(a) : "l"(p));
    return a;
}
__device__ __forceinline__ uint32_t mapa_u32(uint32_t addr, uint32_t rank) {
    uint32_t r;
    asm("mapa.shared::cluster.u32 %0, %1, %2;" : "=r"(r) : "r"(addr), "r"(rank));
    return r;
}
__device__ __forceinline__ void fma2(unsigned long long& acc,
                                     unsigned long long a, unsigned long long b) {
    asm("fma.rn.f32x2 %0, %1, %2, %0;" : "+l"(acc) : "l"(a), "l"(b));
}
__device__ __forceinline__ float acc2_sum(unsigned long long acc) {
    float lo, hi;
    asm("mov.b64 {%0, %1}, %2;" : "=f"(lo), "=f"(hi) : "l"(acc));
    return lo + hi;
}
__device__ __forceinline__ unsigned long long pack2(float a, float b) {
    unsigned long long r;
    asm("mov.b64 %0, {%1, %2};" : "=l"(r) : "f"(a), "f"(b));
    return r;
}
__device__ __forceinline__ void unpack2(unsigned long long v, float& a, float& b) {
    asm("mov.b64 {%0, %1}, %2;" : "=f"(a), "=f"(b) : "l"(v));
}
__device__ __forceinline__ void add2(unsigned long long& acc, unsigned long long v) {
    asm("add.rn.f32x2 %0, %0, %1;" : "+l"(acc) : "l"(v));
}
__device__ __forceinline__ int ld_acq_gpu(const int* p) {
    int v;
    asm volatile("ld.acquire.gpu.global.b32 %0, [%1];" : "=r"(v) : "l"(p) : "memory");
    return v;
}

// Reduce 4 packed (A,B) row-sums across the warp; store to gates.
__device__ __forceinline__ void reduce4_store(unsigned long long v0, unsigned long long v1,
                                              unsigned long long v2, unsigned long long v3,
                                              float* gates, int rows_c, int row0, int lane) {
    add2(v0, __shfl_xor_sync(0xffffffffu, v0, 16));
    add2(v1, __shfl_xor_sync(0xffffffffu, v1, 16));
    add2(v2, __shfl_xor_sync(0xffffffffu, v2, 16));
    add2(v3, __shfl_xor_sync(0xffffffffu, v3, 16));
    add2(v0, __shfl_xor_sync(0xffffffffu, v0, 8));
    add2(v1, __shfl_xor_sync(0xffffffffu, v1, 8));
    add2(v2, __shfl_xor_sync(0xffffffffu, v2, 8));
    add2(v3, __shfl_xor_sync(0xffffffffu, v3, 8));
    const int j = lane >> 3;
    unsigned long long val = v0;
    if (j == 1) val = v1;
    if (j == 2) val = v2;
    if (j == 3) val = v3;
    add2(val, __shfl_xor_sync(0xffffffffu, val, 4));
    add2(val, __shfl_xor_sync(0xffffffffu, val, 2));
    add2(val, __shfl_xor_sync(0xffffffffu, val, 1));
    if ((lane & 7) == 0) {
        float fA, fB;
        unpack2(val, fA, fB);
        gates[row0 + j] = fA;
        gates[rows_c + row0 + j] = fB;
    }
}

#define MBAR_INIT(addr, cnt) \
    asm volatile("mbarrier.init.shared.b64 [%0], %1;" :: "r"(addr), "r"(cnt) : "memory")
#define MBAR_EXPECT_TX(addr, tx) \
    asm volatile("mbarrier.arrive.expect_tx.shared.b64 _, [%0], %1;" :: "r"(addr), "r"(tx) : "memory")
#define MBAR_WAIT_PARITY(addr, ph) do {                                              \
    uint32_t _m = (addr), _p = (ph), _d;                                             \
    asm volatile("{\n\t.reg .pred p;\n\t"                                            \
        "mbarrier.try_wait.parity.acquire.cta.shared::cta.b64 p, [%1], %2;\n\t"      \
        "selp.b32 %0, 1, 0, p;\n\t}"                                                 \
        : "=r"(_d) : "r"(_m), "r"(_p) : "memory");                                   \
    if (!_d) {                                                                        \
        asm volatile("{\n\t.reg .pred P1;\n\t"                                       \
            "WL_%=:\n\t"                                                              \
            "mbarrier.try_wait.parity.acquire.cta.shared::cta.b64 P1, [%0], %1, 0x989680;\n\t" \
            "@P1 bra.uni WD_%=;\n\t"                                                  \
            "bra.uni WL_%=;\n\t"                                                      \
            "WD_%=:\n\t}"                                                             \
            :: "r"(_m), "r"(_p) : "memory");                                          \
    }                                                                                 \
} while (0)

// ---------------- init: zero tile counters -----------------------------------------
__global__ void init_kernel() {
    int i = threadIdx.x;
    if (i < 128) ((int*)g_tile_cnt)[i] = 0;
}

// ---------------- standalone gx GEMM (fallback path), 256 threads ------------------
__global__ void gemm_gx_kernel(const int* __restrict__ sA, const int* __restrict__ sB,
                               const float* __restrict__ emb,
                               const float* __restrict__ w_ih,
                               const float* __restrict__ b_ih,
                               const float* __restrict__ b_hh)
{
    const int t0 = blockIdx.x * 64;
    const int r0 = blockIdx.y * 64;
    const int s  = blockIdx.z;
    const int* sent = s ? sB : sA;
    const int d = r0 >> 11;

    __shared__ float As[32][65];
    __shared__ float Bs[32][65];
    __shared__ int   toks[64];

    const int tid = threadIdx.x;
    const int ty = tid >> 4, tx = tid & 15;

    if (tid < 64) toks[tid] = sent[t0 + tid];
    __syncthreads();

    float acc[4][4] = {};

    for (int k0 = 0; k0 < EE; k0 += 32) {
#pragma unroll
        for (int m = 0; m < 8; ++m) {
            int idx = tid + m * 256;
            int tt = idx >> 5, kk = idx & 31;
            int k = k0 + kk;
            As[kk][tt] = (k < EE) ? emb[(size_t)toks[tt] * EE + k] : 0.f;
        }
#pragma unroll
        for (int m = 0; m < 8; ++m) {
            int idx = tid + m * 256;
            int rr = idx >> 5, kk = idx & 31;
            int k = k0 + kk;
            Bs[kk][rr] = (k < EE) ? w_ih[(size_t)(r0 + rr) * EE + k] : 0.f;
        }
        __syncthreads();
#pragma unroll
        for (int kk = 0; kk < 32; ++kk) {
            float a0 = As[kk][ty * 4 + 0], a1 = As[kk][ty * 4 + 1];
            float a2 = As[kk][ty * 4 + 2], a3 = As[kk][ty * 4 + 3];
            float b0 = Bs[kk][tx + 16 * 0], b1 = Bs[kk][tx + 16 * 1];
            float b2 = Bs[kk][tx + 16 * 2], b3 = Bs[kk][tx + 16 * 3];
            acc[0][0] += a0 * b0; acc[0][1] += a0 * b1; acc[0][2] += a0 * b2; acc[0][3] += a0 * b3;
            acc[1][0] += a1 * b0; acc[1][1] += a1 * b1; acc[1][2] += a1 * b2; acc[1][3] += a1 * b3;
            acc[2][0] += a2 * b0; acc[2][1] += a2 * b1; acc[2][2] += a2 * b2; acc[2][3] += a2 * b3;
            acc[3][0] += a3 * b0; acc[3][1] += a3 * b1; acc[3][2] += a3 * b2; acc[3][3] += a3 * b3;
        }
        __syncthreads();
    }

#pragma unroll
    for (int i = 0; i < 4; ++i) {
        int t = t0 + ty * 4 + i;
        int tstore = d ? (TT - 1 - t) : t;
        size_t rowbase = (((size_t)(d * 2 + s)) * TT + tstore) * 2048;
#pragma unroll
        for (int j = 0; j < 4; ++j) {
            int r = r0 + tx + 16 * j;
            g_gx[rowbase + (r & 2047)] = acc[i][j] + b_ih[r] + b_hh[r];
        }
    }
}

// ---------------- worker body: gx GEMM tiles with 512 threads ----------------------
__device__ void worker_body(int widx, int nwork, char* smem_raw,
                            const int* sA, const int* sB,
                            const float* emb, const float* w_ih,
                            const float* b_ih, const float* b_hh)
{
    float* As = reinterpret_cast<float*>(smem_raw);              // [32][65]
    float* Bs = As + 32 * 65;                                    // [32][65]
    int*   toks = reinterpret_cast<int*>(Bs + 32 * 65);          // [64]

    const int tid = threadIdx.x;
    const int ty = tid >> 4;          // 0..31 (2 t-rows each)
    const int tx = tid & 15;

    for (int i = widx; i < 4096; i += nwork) {
        const int stt = i >> 7;
        const int sub = i & 127;
        const int y   = sub >> 1;
        const int s   = sub & 1;
        const int d   = y >> 5;
        const int t0  = (d ? (31 - stt) : stt) << 6;
        const int r0  = y << 6;
        const int* sent = s ? sB : sA;

        if (tid < 64) toks[tid] = sent[t0 + tid];
        __syncthreads();

        float acc[2][4] = {};

        for (int k0 = 0; k0 < EE; k0 += 32) {
#pragma unroll
            for (int m = 0; m < 4; ++m) {
                int idx = tid + m * 512;
                int tt = idx >> 5, kk = idx & 31;
                int k = k0 + kk;
                As[kk * 65 + tt] = (k < EE) ? emb[(size_t)toks[tt] * EE + k] : 0.f;
            }
#pragma unroll
            for (int m = 0; m < 4; ++m) {
                int idx = tid + m * 512;
                int rr = idx >> 5, kk = idx & 31;
                int k = k0 + kk;
                Bs[kk * 65 + rr] = (k < EE) ? w_ih[(size_t)(r0 + rr) * EE + k] : 0.f;
            }
            __syncthreads();
#pragma unroll
            for (int kk = 0; kk < 32; ++kk) {
                float a0 = As[kk * 65 + ty * 2 + 0];
                float a1 = As[kk * 65 + ty * 2 + 1];
                float b0 = Bs[kk * 65 + tx + 16 * 0], b1 = Bs[kk * 65 + tx + 16 * 1];
                float b2 = Bs[kk * 65 + tx + 16 * 2], b3 = Bs[kk * 65 + tx + 16 * 3];
                acc[0][0] += a0 * b0; acc[0][1] += a0 * b1; acc[0][2] += a0 * b2; acc[0][3] += a0 * b3;
                acc[1][0] += a1 * b0; acc[1][1] += a1 * b1; acc[1][2] += a1 * b2; acc[1][3] += a1 * b3;
            }
            __syncthreads();
        }

#pragma unroll
        for (int ii = 0; ii < 2; ++ii) {
            int t = t0 + ty * 2 + ii;
            int tstore = d ? (TT - 1 - t) : t;
            size_t rowbase = (((size_t)(d * 2 + s)) * TT + tstore) * 2048;
#pragma unroll
            for (int j = 0; j < 4; ++j) {
                int r = r0 + tx + 16 * j;
                g_gx[rowbase + (r & 2047)] = acc[ii][j] + b_ih[r] + b_hh[r];
            }
        }
        __syncthreads();
        if (tid == 0) {
            __threadfence();
            atomicAdd(&g_tile_cnt[d * 2 + s][stt], 1);
        }
        __syncthreads();
    }
}

// ---------------- fused kernel: LSTM clusters + GEMM worker clusters ---------------
// LSTM core identical to R12; REG_ROWS=3 / SMEM_ROWS=5 (one more register-resident
// weight row per warp; -32KB/step off the LDS crossbar).
template <int CSZ>
__global__ void __launch_bounds__(512, 1)
lstm_fused_kernel(const float* __restrict__ w_hh,
                  const int* __restrict__ sA, const int* __restrict__ sB,
                  const float* __restrict__ emb, const float* __restrict__ w_ih,
                  const float* __restrict__ b_ih, const float* __restrict__ b_hh,
                  int wait_tiles, int n_worker_ctas)
{
    extern __shared__ float smf[];

    if (blockIdx.x >= 2 * CSZ) {
        worker_body(blockIdx.x - 2 * CSZ, n_worker_ctas, reinterpret_cast<char*>(smf),
                    sA, sB, emb, w_ih, b_ih, b_hh);
        return;
    }

    constexpr int NT   = 512;
    constexpr int NW   = 16;
    constexpr int UPC  = HH / CSZ;
    constexpr int ROWS = 4 * UPC;
    constexpr int RPW  = ROWS / NW;
    constexpr int REG_ROWS  = 3;
    constexpr int SMEM_ROWS = 5;
    constexpr int UIT  = UPC / 32;
    constexpr int CHUNK = UPC * 4;
    constexpr uint32_t TX_TOTAL = 2 * HH * 4;

    float* w_sm  = smf;                                     // NW*SMEM_ROWS*HH
    float* h_s   = w_sm + NW * SMEM_ROWS * HH;              // [2][2*HH]
    float* gates = h_s + 4 * HH;                            // [2][ROWS]
    float* stage = gates + 2 * ROWS;                        // [2][2*UPC]
    unsigned long long* s_bar = reinterpret_cast<unsigned long long*>(stage + 4 * UPC);

    const int tid  = threadIdx.x;
    const int lane = tid & 31;
    const int wid  = tid >> 5;
    const int dir  = blockIdx.x / CSZ;
    const int rank = blockIdx.x % CSZ;
    const int ku   = rank * UPC;

    for (int i = tid; i < 2 * HH; i += NT) h_s[i] = 0.f;
    if (tid == 0) {
        MBAR_INIT(smem_u32(&s_bar[0]), 1);
        MBAR_INIT(smem_u32(&s_bar[1]), 1);
    }

    const float* wbase = w_hh + (size_t)dir * 2048 * HH;
    const int r_first = wid * RPW;
    const float* wrow0 = wbase + ((size_t)(r_first / UPC) * HH + ku + (r_first % UPC)) * HH;

    for (int j = 0; j < SMEM_ROWS; ++j) {
        const float4* src = reinterpret_cast<const float4*>(wrow0 + (size_t)(REG_ROWS + j) * HH);
        float4* dst = reinterpret_cast<float4*>(w_sm + (size_t)(wid * SMEM_ROWS + j) * HH);
        for (int i = lane; i < HH / 4; i += 32) dst[i] = src[i];
    }

    ulonglong2 wreg[REG_ROWS][4];
#pragma unroll
    for (int j = 0; j < REG_ROWS; ++j) {
        const ulonglong2* wr = reinterpret_cast<const ulonglong2*>(wrow0 + (size_t)j * HH);
#pragma unroll
        for (int i = 0; i < 4; ++i) wreg[j][i] = wr[lane + 32 * i];
    }

    __syncthreads();
    asm volatile("barrier.cluster.arrive.aligned;" ::: "memory");
    asm volatile("barrier.cluster.wait.aligned;"   ::: "memory");

    const uint32_t bar_a[2]  = { smem_u32(&s_bar[0]), smem_u32(&s_bar[1]) };
    const uint32_t hbuf_a[2] = { smem_u32(h_s), smem_u32(h_s + 2 * HH) };
    const uint32_t stage_a   = smem_u32(stage);

    const ulonglong2* wsm2 = reinterpret_cast<const ulonglong2*>(
        w_sm + (size_t)(wid * SMEM_ROWS) * HH);

    float c_st[UIT];
#pragma unroll
    for (int i = 0; i < UIT; ++i) c_st[i] = 0.f;

    for (int t = 0; t < TT; ++t) {
        const int rb = t & 1;
        const int wb = (t + 1) & 1;
        const int bi = t & 1;
        const int ph = (t >> 1) & 1;

        if (wait_tiles && (t & 63) == 0) {
            const int tt = t >> 6;
            const int* c0 = &g_tile_cnt[dir * 2 + 0][tt];
            const int* c1 = &g_tile_cnt[dir * 2 + 1][tt];
            while (ld_acq_gpu(c0) < 32) {}
            while (ld_acq_gpu(c1) < 32) {}
        }

        if (tid == 0) MBAR_EXPECT_TX(bar_a[bi], TX_TOTAL);

        float gxv[UIT][4];
        if (wid < 2) {
            const float* px = g_gx + ((size_t)(dir * 2 + wid) * TT + t) * 2048 + ku;
#pragma unroll
            for (int it = 0; it < UIT; ++it) {
                int u = lane + 32 * it;
#pragma unroll
                for (int g = 0; g < 4; ++g) gxv[it][g] = __ldg(px + g * HH + u);
            }
        }

        const ulonglong2* hA2 = reinterpret_cast<const ulonglong2*>(h_s + rb * 2 * HH);
        const ulonglong2* hB2 = reinterpret_cast<const ulonglong2*>(h_s + rb * 2 * HH + HH);
        ulonglong2 ha[4], hb[4];
#pragma unroll
        for (int i = 0; i < 4; ++i) {
            ha[i] = hA2[lane + 32 * i];
            hb[i] = hB2[lane + 32 * i];
        }

#pragma unroll
        for (int b = 0; b < RPW / 4; ++b) {
            unsigned long long aA[4] = {0,0,0,0}, aB[4] = {0,0,0,0};
#pragma unroll
            for (int r = 0; r < 4; ++r) {
                const int j = 4 * b + r;
                ulonglong2 wv0, wv1, wv2, wv3;
                if (j < REG_ROWS) {
                    wv0 = wreg[j][0]; wv1 = wreg[j][1]; wv2 = wreg[j][2]; wv3 = wreg[j][3];
                } else if (j < REG_ROWS + SMEM_ROWS) {
                    const ulonglong2* wr = wsm2 + (size_t)(j - REG_ROWS) * (HH / 4);
                    wv0 = wr[lane]; wv1 = wr[lane + 32]; wv2 = wr[lane + 64]; wv3 = wr[lane + 96];
                } else {
                    const ulonglong2* wr = reinterpret_cast<const ulonglong2*>(
                        wrow0 + (size_t)j * HH);
                    wv0 = wr[lane]; wv1 = wr[lane + 32]; wv2 = wr[lane + 64]; wv3 = wr[lane + 96];
                }
                fma2(aA[r], wv0.x, ha[0].x); fma2(aA[r], wv0.y, ha[0].y);
                fma2(aA[r], wv1.x, ha[1].x); fma2(aA[r], wv1.y, ha[1].y);
                fma2(aA[r], wv2.x, ha[2].x); fma2(aA[r], wv2.y, ha[2].y);
                fma2(aA[r], wv3.x, ha[3].x); fma2(aA[r], wv3.y, ha[3].y);
                fma2(aB[r], wv0.x, hb[0].x); fma2(aB[r], wv0.y, hb[0].y);
                fma2(aB[r], wv1.x, hb[1].x); fma2(aB[r], wv1.y, hb[1].y);
                fma2(aB[r], wv2.x, hb[2].x); fma2(aB[r], wv2.y, hb[2].y);
                fma2(aB[r], wv3.x, hb[3].x); fma2(aB[r], wv3.y, hb[3].y);
            }
            reduce4_store(pack2(acc2_sum(aA[0]), acc2_sum(aB[0])),
                          pack2(acc2_sum(aA[1]), acc2_sum(aB[1])),
                          pack2(acc2_sum(aA[2]), acc2_sum(aB[2])),
                          pack2(acc2_sum(aA[3]), acc2_sum(aB[3])),
                          gates, ROWS, r_first + 4 * b, lane);
        }

        __syncthreads();   // gates complete (only CTA barrier per step)

        if (wid < 2) {
            const int sb = t & 1;
            float* stg = stage + sb * 2 * UPC + wid * UPC;
#pragma unroll
            for (int it = 0; it < UIT; ++it) {
                int u = lane + 32 * it;
                float g0 = gates[wid * ROWS + 0 * UPC + u] + gxv[it][0];
                float g1 = gates[wid * ROWS + 1 * UPC + u] + gxv[it][1];
                float g2 = gates[wid * ROWS + 2 * UPC + u] + gxv[it][2];
                float g3 = gates[wid * ROWS + 3 * UPC + u] + gxv[it][3];
                c_st[it] = sigf(g1) * c_st[it] + sigf(g0) * tanh_fast(g2);
                float hv = sigf(g3) * tanh_fast(c_st[it]);
                stg[u] = hv;
                if (t == TT - 1) g_h[0][dir][wid][ku + u] = hv;
            }
            __syncwarp();
            asm volatile("fence.proxy.async.shared::cta;" ::: "memory");
            if (lane < CSZ) {
                uint32_t src  = stage_a + ((t & 1) * 2 * UPC + wid * UPC) * 4;
                uint32_t ldst = hbuf_a[wb] + (wid * HH + ku) * 4;
                uint32_t rdst = mapa_u32(ldst, (uint32_t)lane);
                uint32_t rbar = mapa_u32(bar_a[bi], (uint32_t)lane);
                asm volatile(
                    "cp.async.bulk.shared::cluster.shared::cta.mbarrier::complete_tx::bytes "
                    "[%0], [%1], %2, [%3];"
                    :: "r"(rdst), "r"(src), "n"(CHUNK), "r"(rbar) : "memory");
            }
        }

        MBAR_WAIT_PARITY(bar_a[bi], (uint32_t)ph);
    }
}

// ---------------- phase 3: head ------------------------------------------------------
__global__ void head_kernel(const float* __restrict__ bi_w, const float* __restrict__ bi_b,
                            const float* __restrict__ blA, const float* __restrict__ blB,
                            const float* __restrict__ bl_b,
                            const float* __restrict__ out_w, const float* __restrict__ out_b,
                            float* __restrict__ out)
{
    __shared__ float hA[HH], hB[HH];
    __shared__ float red[16];
    const int j = threadIdx.x;
    const float w0 = bi_w[0], w1 = bi_w[1], bb = bi_b[0];

    hA[j] = w0 * g_h[0][0][0][j] + w1 * g_h[0][1][0][j] + bb;
    hB[j] = w0 * g_h[0][0][1][j] + w1 * g_h[0][1][1][j] + bb;
    __syncthreads();

    float acc = bl_b[j];
#pragma unroll 4
    for (int i = 0; i < HH; ++i)
        acc += hA[i] * blA[(size_t)i * HH + j] + hB[i] * blB[(size_t)i * HH + j];

    float v = tanhf(acc) * out_w[j];
#pragma unroll
    for (int off = 16; off; off >>= 1) v += __shfl_xor_sync(0xffffffffu, v, off);
    if ((j & 31) == 0) red[j >> 5] = v;
    __syncthreads();
    if (j < 16) {
        float r = red[j];
#pragma unroll
        for (int off = 8; off; off >>= 1) r += __shfl_xor_sync(0x0000ffffu, r, off);
        if (j == 0) out[0] = 1.f / (1.f + expf(-(r + out_b[0])));
    }
}

// ---------------- launch --------------------------------------------------------------
extern "C" void kernel_launch(void* const* d_in, const int* in_sizes, int n_in,
                              void* d_out, int out_size)
{
    (void)in_sizes; (void)n_in; (void)out_size;
    const int*   sentA = (const int*)d_in[0];
    const int*   sentB = (const int*)d_in[1];
    const float* emb   = (const float*)d_in[3];
    const float* w_ih  = (const float*)d_in[4];
    const float* w_hh  = (const float*)d_in[5];
    const float* b_ih  = (const float*)d_in[6];
    const float* b_hh  = (const float*)d_in[7];
    const float* bi_w  = (const float*)d_in[8];
    const float* bi_b  = (const float*)d_in[9];
    const float* blA   = (const float*)d_in[10];
    const float* blB   = (const float*)d_in[11];
    const float* bl_b  = (const float*)d_in[12];
    const float* out_w = (const float*)d_in[13];
    const float* out_b = (const float*)d_in[14];
    float* out = (float*)d_out;

    auto smem_for = [](int csz) {
        int upc = HH / csz, rows = 4 * upc;
        return (int)((16 * 5 * HH + 4 * HH + 2 * rows + 4 * upc) * sizeof(float)) + 16;
    };
    const int smem16 = smem_for(16);
    const int smem8  = smem_for(8);

    cudaFuncSetAttribute(lstm_fused_kernel<16>,
                         cudaFuncAttributeNonPortableClusterSizeAllowed, 1);
    cudaFuncSetAttribute(lstm_fused_kernel<16>,
                         cudaFuncAttributeMaxDynamicSharedMemorySize, smem16);
    cudaFuncSetAttribute(lstm_fused_kernel<8>,
                         cudaFuncAttributeMaxDynamicSharedMemorySize, smem8);

    cudaLaunchConfig_t cfg = {};
    cfg.blockDim = dim3(512, 1, 1);
    cfg.stream = 0;
    cudaLaunchAttribute attr[1];
    attr[0].id = cudaLaunchAttributeClusterDimension;
    cfg.attrs = attr;
    cfg.numAttrs = 1;

    cfg.gridDim = dim3(2 * 16, 1, 1);
    cfg.dynamicSmemBytes = smem16;
    attr[0].val.clusterDim.x = 16; attr[0].val.clusterDim.y = 1; attr[0].val.clusterDim.z = 1;

    int ncl = 0;
    cudaError_t e = cudaOccupancyMaxActiveClusters(&ncl, lstm_fused_kernel<16>, &cfg);
    if (e == cudaSuccess && ncl >= 3) {
        int use = ncl < 9 ? ncl : 9;
        int nworkers = (use - 2) * 16;
        cfg.gridDim = dim3(use * 16, 1, 1);
        init_kernel<<<1, 128>>>();
        cudaLaunchKernelEx(&cfg, lstm_fused_kernel<16>,
                           w_hh, sentA, sentB, emb, w_ih, b_ih, b_hh, 1, nworkers);
    } else {
        (void)cudaGetLastError();
        gemm_gx_kernel<<<dim3(32, 64, 2), 256>>>(sentA, sentB, emb, w_ih, b_ih, b_hh);
        if (e == cudaSuccess && ncl >= 1) {
            cfg.gridDim = dim3(2 * 16, 1, 1);
            cudaLaunchKernelEx(&cfg, lstm_fused_kernel<16>,
                               w_hh, sentA, sentB, emb, w_ih, b_ih, b_hh, 0, 0);
        } else {
            (void)cudaGetLastError();
            cfg.gridDim = dim3(2 * 8, 1, 1);
            cfg.dynamicSmemBytes = smem8;
            attr[0].val.clusterDim.x = 8;
            cudaLaunchKernelEx(&cfg, lstm_fused_kernel<8>,
                               w_hh, sentA, sentB, emb, w_ih, b_ih, b_hh, 0, 0);
        }
    }

    head_kernel<<<1, 512>>>(bi_w, bi_b, blA, blB, bl_b, out_w, out_b, out);
}

// round 15
// speedup vs baseline: 1.3875x; 1.0639x over previous
#include <cuda_runtime.h>
#include <cuda_bf16.h>
#include <cstdint>
#include <cstddef>

#define TT   2048
#define EE   300
#define HH   512

__device__ float g_gx[(size_t)4 * TT * 2048];   // [dir*2+sent][t][4H]
__device__ float g_h[2][2][2][HH];              // [parity][dir][sent][H]
__device__ int   g_tile_cnt[4][32];             // [dir*2+sent][stored t-tile] -> 32 when ready

__device__ __forceinline__ float sigf(float x) { return 1.f / (1.f + __expf(-x)); }
__device__ __forceinline__ float tanh_hw(float x) {
    float r;
    asm("tanh.approx.f32 %0, %1;" : "=f"(r) : "f"(x));
    return r;
}

__device__ __forceinline__ uint32_t smem_u32(const void* p) {
    uint32_t a;
    asm("{ .reg .u64 t; cvta.to.shared.u64 t, %1; cvt.u32.u64 %0, t; }" : "=r"(a) : "l"(p));
    return a;
}
__device__ __forceinline__ uint32_t mapa_u32(uint32_t addr, uint32_t rank) {
    uint32_t r;
    asm("mapa.shared::cluster.u32 %0, %1, %2;" : "=r"(r) : "r"(addr), "r"(rank));
    return r;
}
__device__ __forceinline__ void fma2(unsigned long long& acc,
                                     unsigned long long a, unsigned long long b) {
    asm("fma.rn.f32x2 %0, %1, %2, %0;" : "+l"(acc) : "l"(a), "l"(b));
}
__device__ __forceinline__ float acc2_sum(unsigned long long acc) {
    float lo, hi;
    asm("mov.b64 {%0, %1}, %2;" : "=f"(lo), "=f"(hi) : "l"(acc));
    return lo + hi;
}
__device__ __forceinline__ unsigned long long pack2(float a, float b) {
    unsigned long long r;
    asm("mov.b64 %0, {%1, %2};" : "=l"(r) : "f"(a), "f"(b));
    return r;
}
__device__ __forceinline__ void unpack2(unsigned long long v, float& a, float& b) {
    asm("mov.b64 {%0, %1}, %2;" : "=f"(a), "=f"(b) : "l"(v));
}
__device__ __forceinline__ void add2(unsigned long long& acc, unsigned long long v) {
    asm("add.rn.f32x2 %0, %0, %1;" : "+l"(acc) : "l"(v));
}
__device__ __forceinline__ int ld_acq_gpu(const int* p) {
    int v;
    asm volatile("ld.acquire.gpu.global.b32 %0, [%1];" : "=r"(v) : "l"(p) : "memory");
    return v;
}

// Reduce 4 packed (A,B) row-sums across the warp; store to gates.
__device__ __forceinline__ void reduce4_store(unsigned long long v0, unsigned long long v1,
                                              unsigned long long v2, unsigned long long v3,
                                              float* gates, int rows_c, int row0, int lane) {
    add2(v0, __shfl_xor_sync(0xffffffffu, v0, 16));
    add2(v1, __shfl_xor_sync(0xffffffffu, v1, 16));
    add2(v2, __shfl_xor_sync(0xffffffffu, v2, 16));
    add2(v3, __shfl_xor_sync(0xffffffffu, v3, 16));
    add2(v0, __shfl_xor_sync(0xffffffffu, v0, 8));
    add2(v1, __shfl_xor_sync(0xffffffffu, v1, 8));
    add2(v2, __shfl_xor_sync(0xffffffffu, v2, 8));
    add2(v3, __shfl_xor_sync(0xffffffffu, v3, 8));
    const int j = lane >> 3;
    unsigned long long val = v0;
    if (j == 1) val = v1;
    if (j == 2) val = v2;
    if (j == 3) val = v3;
    add2(val, __shfl_xor_sync(0xffffffffu, val, 4));
    add2(val, __shfl_xor_sync(0xffffffffu, val, 2));
    add2(val, __shfl_xor_sync(0xffffffffu, val, 1));
    if ((lane & 7) == 0) {
        float fA, fB;
        unpack2(val, fA, fB);
        gates[row0 + j] = fA;
        gates[rows_c + row0 + j] = fB;
    }
}

#define MBAR_INIT(addr, cnt) \
    asm volatile("mbarrier.init.shared.b64 [%0], %1;" :: "r"(addr), "r"(cnt) : "memory")
#define MBAR_EXPECT_TX(addr, tx) \
    asm volatile("mbarrier.arrive.expect_tx.shared.b64 _, [%0], %1;" :: "r"(addr), "r"(tx) : "memory")
#define MBAR_WAIT_PARITY(addr, ph) do {                                              \
    uint32_t _m = (addr), _p = (ph), _d;                                             \
    asm volatile("{\n\t.reg .pred p;\n\t"                                            \
        "mbarrier.try_wait.parity.acquire.cta.shared::cta.b64 p, [%1], %2;\n\t"      \
        "selp.b32 %0, 1, 0, p;\n\t}"                                                 \
        : "=r"(_d) : "r"(_m), "r"(_p) : "memory");                                   \
    if (!_d) {                                                                        \
        asm volatile("{\n\t.reg .pred P1;\n\t"                                       \
            "WL_%=:\n\t"                                                              \
            "mbarrier.try_wait.parity.acquire.cta.shared::cta.b64 P1, [%0], %1, 0x989680;\n\t" \
            "@P1 bra.uni WD_%=;\n\t"                                                  \
            "bra.uni WL_%=;\n\t"                                                      \
            "WD_%=:\n\t}"                                                             \
            :: "r"(_m), "r"(_p) : "memory");                                          \
    }                                                                                 \
} while (0)

// ---------------- init: zero tile counters -----------------------------------------
__global__ void init_kernel() {
    int i = threadIdx.x;
    if (i < 128) ((int*)g_tile_cnt)[i] = 0;
}

// ---------------- standalone gx GEMM (fallback path), 256 threads ------------------
__global__ void gemm_gx_kernel(const int* __restrict__ sA, const int* __restrict__ sB,
                               const float* __restrict__ emb,
                               const float* __restrict__ w_ih,
                               const float* __restrict__ b_ih,
                               const float* __restrict__ b_hh)
{
    const int t0 = blockIdx.x * 64;
    const int r0 = blockIdx.y * 64;
    const int s  = blockIdx.z;
    const int* sent = s ? sB : sA;
    const int d = r0 >> 11;

    __shared__ float As[32][65];
    __shared__ float Bs[32][65];
    __shared__ int   toks[64];

    const int tid = threadIdx.x;
    const int ty = tid >> 4, tx = tid & 15;

    if (tid < 64) toks[tid] = sent[t0 + tid];
    __syncthreads();

    float acc[4][4] = {};

    for (int k0 = 0; k0 < EE; k0 += 32) {
#pragma unroll
        for (int m = 0; m < 8; ++m) {
            int idx = tid + m * 256;
            int tt = idx >> 5, kk = idx & 31;
            int k = k0 + kk;
            As[kk][tt] = (k < EE) ? emb[(size_t)toks[tt] * EE + k] : 0.f;
        }
#pragma unroll
        for (int m = 0; m < 8; ++m) {
            int idx = tid + m * 256;
            int rr = idx >> 5, kk = idx & 31;
            int k = k0 + kk;
            Bs[kk][rr] = (k < EE) ? w_ih[(size_t)(r0 + rr) * EE + k] : 0.f;
        }
        __syncthreads();
#pragma unroll
        for (int kk = 0; kk < 32; ++kk) {
            float a0 = As[kk][ty * 4 + 0], a1 = As[kk][ty * 4 + 1];
            float a2 = As[kk][ty * 4 + 2], a3 = As[kk][ty * 4 + 3];
            float b0 = Bs[kk][tx + 16 * 0], b1 = Bs[kk][tx + 16 * 1];
            float b2 = Bs[kk][tx + 16 * 2], b3 = Bs[kk][tx + 16 * 3];
            acc[0][0] += a0 * b0; acc[0][1] += a0 * b1; acc[0][2] += a0 * b2; acc[0][3] += a0 * b3;
            acc[1][0] += a1 * b0; acc[1][1] += a1 * b1; acc[1][2] += a1 * b2; acc[1][3] += a1 * b3;
            acc[2][0] += a2 * b0; acc[2][1] += a2 * b1; acc[2][2] += a2 * b2; acc[2][3] += a2 * b3;
            acc[3][0] += a3 * b0; acc[3][1] += a3 * b1; acc[3][2] += a3 * b2; acc[3][3] += a3 * b3;
        }
        __syncthreads();
    }

#pragma unroll
    for (int i = 0; i < 4; ++i) {
        int t = t0 + ty * 4 + i;
        int tstore = d ? (TT - 1 - t) : t;
        size_t rowbase = (((size_t)(d * 2 + s)) * TT + tstore) * 2048;
#pragma unroll
        for (int j = 0; j < 4; ++j) {
            int r = r0 + tx + 16 * j;
            g_gx[rowbase + (r & 2047)] = acc[i][j] + b_ih[r] + b_hh[r];
        }
    }
}

// ---------------- worker body: gx GEMM tiles with 512 threads ----------------------
__device__ void worker_body(int widx, int nwork, char* smem_raw,
                            const int* sA, const int* sB,
                            const float* emb, const float* w_ih,
                            const float* b_ih, const float* b_hh)
{
    float* As = reinterpret_cast<float*>(smem_raw);              // [32][65]
    float* Bs = As + 32 * 65;                                    // [32][65]
    int*   toks = reinterpret_cast<int*>(Bs + 32 * 65);          // [64]

    const int tid = threadIdx.x;
    const int ty = tid >> 4;          // 0..31 (2 t-rows each)
    const int tx = tid & 15;

    for (int i = widx; i < 4096; i += nwork) {
        const int stt = i >> 7;
        const int sub = i & 127;
        const int y   = sub >> 1;
        const int s   = sub & 1;
        const int d   = y >> 5;
        const int t0  = (d ? (31 - stt) : stt) << 6;
        const int r0  = y << 6;
        const int* sent = s ? sB : sA;

        if (tid < 64) toks[tid] = sent[t0 + tid];
        __syncthreads();

        float acc[2][4] = {};

        for (int k0 = 0; k0 < EE; k0 += 32) {
#pragma unroll
            for (int m = 0; m < 4; ++m) {
                int idx = tid + m * 512;
                int tt = idx >> 5, kk = idx & 31;
                int k = k0 + kk;
                As[kk * 65 + tt] = (k < EE) ? emb[(size_t)toks[tt] * EE + k] : 0.f;
            }
#pragma unroll
            for (int m = 0; m < 4; ++m) {
                int idx = tid + m * 512;
                int rr = idx >> 5, kk = idx & 31;
                int k = k0 + kk;
                Bs[kk * 65 + rr] = (k < EE) ? w_ih[(size_t)(r0 + rr) * EE + k] : 0.f;
            }
            __syncthreads();
#pragma unroll
            for (int kk = 0; kk < 32; ++kk) {
                float a0 = As[kk * 65 + ty * 2 + 0];
                float a1 = As[kk * 65 + ty * 2 + 1];
                float b0 = Bs[kk * 65 + tx + 16 * 0], b1 = Bs[kk * 65 + tx + 16 * 1];
                float b2 = Bs[kk * 65 + tx + 16 * 2], b3 = Bs[kk * 65 + tx + 16 * 3];
                acc[0][0] += a0 * b0; acc[0][1] += a0 * b1; acc[0][2] += a0 * b2; acc[0][3] += a0 * b3;
                acc[1][0] += a1 * b0; acc[1][1] += a1 * b1; acc[1][2] += a1 * b2; acc[1][3] += a1 * b3;
            }
            __syncthreads();
        }

#pragma unroll
        for (int ii = 0; ii < 2; ++ii) {
            int t = t0 + ty * 2 + ii;
            int tstore = d ? (TT - 1 - t) : t;
            size_t rowbase = (((size_t)(d * 2 + s)) * TT + tstore) * 2048;
#pragma unroll
            for (int j = 0; j < 4; ++j) {
                int r = r0 + tx + 16 * j;
                g_gx[rowbase + (r & 2047)] = acc[ii][j] + b_ih[r] + b_hh[r];
            }
        }
        __syncthreads();
        if (tid == 0) {
            __threadfence();
            atomicAdd(&g_tile_cnt[d * 2 + s][stt], 1);
        }
        __syncthreads();
    }
}

// ---------------- fused kernel: LSTM clusters + GEMM worker clusters ---------------
// LSTM core = R12 exactly (REG_ROWS=2 / SMEM_ROWS=6); tail tanh via tanh.approx.
template <int CSZ>
__global__ void __launch_bounds__(512, 1)
lstm_fused_kernel(const float* __restrict__ w_hh,
                  const int* __restrict__ sA, const int* __restrict__ sB,
                  const float* __restrict__ emb, const float* __restrict__ w_ih,
                  const float* __restrict__ b_ih, const float* __restrict__ b_hh,
                  int wait_tiles, int n_worker_ctas)
{
    extern __shared__ float smf[];

    if (blockIdx.x >= 2 * CSZ) {
        worker_body(blockIdx.x - 2 * CSZ, n_worker_ctas, reinterpret_cast<char*>(smf),
                    sA, sB, emb, w_ih, b_ih, b_hh);
        return;
    }

    constexpr int NT   = 512;
    constexpr int NW   = 16;
    constexpr int UPC  = HH / CSZ;
    constexpr int ROWS = 4 * UPC;
    constexpr int RPW  = ROWS / NW;
    constexpr int REG_ROWS  = 2;
    constexpr int SMEM_ROWS = 6;
    constexpr int UIT  = UPC / 32;
    constexpr int CHUNK = UPC * 4;
    constexpr uint32_t TX_TOTAL = 2 * HH * 4;

    float* w_sm  = smf;                                     // NW*SMEM_ROWS*HH
    float* h_s   = w_sm + NW * SMEM_ROWS * HH;              // [2][2*HH]
    float* gates = h_s + 4 * HH;                            // [2][ROWS]
    float* stage = gates + 2 * ROWS;                        // [2][2*UPC]
    unsigned long long* s_bar = reinterpret_cast<unsigned long long*>(stage + 4 * UPC);

    const int tid  = threadIdx.x;
    const int lane = tid & 31;
    const int wid  = tid >> 5;
    const int dir  = blockIdx.x / CSZ;
    const int rank = blockIdx.x % CSZ;
    const int ku   = rank * UPC;

    for (int i = tid; i < 2 * HH; i += NT) h_s[i] = 0.f;
    if (tid == 0) {
        MBAR_INIT(smem_u32(&s_bar[0]), 1);
        MBAR_INIT(smem_u32(&s_bar[1]), 1);
    }

    const float* wbase = w_hh + (size_t)dir * 2048 * HH;
    const int r_first = wid * RPW;
    const float* wrow0 = wbase + ((size_t)(r_first / UPC) * HH + ku + (r_first % UPC)) * HH;

    for (int j = 0; j < SMEM_ROWS; ++j) {
        const float4* src = reinterpret_cast<const float4*>(wrow0 + (size_t)(REG_ROWS + j) * HH);
        float4* dst = reinterpret_cast<float4*>(w_sm + (size_t)(wid * SMEM_ROWS + j) * HH);
        for (int i = lane; i < HH / 4; i += 32) dst[i] = src[i];
    }

    ulonglong2 wreg[REG_ROWS][4];
#pragma unroll
    for (int j = 0; j < REG_ROWS; ++j) {
        const ulonglong2* wr = reinterpret_cast<const ulonglong2*>(wrow0 + (size_t)j * HH);
#pragma unroll
        for (int i = 0; i < 4; ++i) wreg[j][i] = wr[lane + 32 * i];
    }

    __syncthreads();
    asm volatile("barrier.cluster.arrive.aligned;" ::: "memory");
    asm volatile("barrier.cluster.wait.aligned;"   ::: "memory");

    const uint32_t bar_a[2]  = { smem_u32(&s_bar[0]), smem_u32(&s_bar[1]) };
    const uint32_t hbuf_a[2] = { smem_u32(h_s), smem_u32(h_s + 2 * HH) };
    const uint32_t stage_a   = smem_u32(stage);

    const ulonglong2* wsm2 = reinterpret_cast<const ulonglong2*>(
        w_sm + (size_t)(wid * SMEM_ROWS) * HH);

    float c_st[UIT];
#pragma unroll
    for (int i = 0; i < UIT; ++i) c_st[i] = 0.f;

    for (int t = 0; t < TT; ++t) {
        const int rb = t & 1;
        const int wb = (t + 1) & 1;
        const int bi = t & 1;
        const int ph = (t >> 1) & 1;

        if (wait_tiles && (t & 63) == 0) {
            const int tt = t >> 6;
            const int* c0 = &g_tile_cnt[dir * 2 + 0][tt];
            const int* c1 = &g_tile_cnt[dir * 2 + 1][tt];
            while (ld_acq_gpu(c0) < 32) {}
            while (ld_acq_gpu(c1) < 32) {}
        }

        if (tid == 0) MBAR_EXPECT_TX(bar_a[bi], TX_TOTAL);

        float gxv[UIT][4];
        if (wid < 2) {
            const float* px = g_gx + ((size_t)(dir * 2 + wid) * TT + t) * 2048 + ku;
#pragma unroll
            for (int it = 0; it < UIT; ++it) {
                int u = lane + 32 * it;
#pragma unroll
                for (int g = 0; g < 4; ++g) gxv[it][g] = __ldg(px + g * HH + u);
            }
        }

        const ulonglong2* hA2 = reinterpret_cast<const ulonglong2*>(h_s + rb * 2 * HH);
        const ulonglong2* hB2 = reinterpret_cast<const ulonglong2*>(h_s + rb * 2 * HH + HH);
        ulonglong2 ha[4], hb[4];
#pragma unroll
        for (int i = 0; i < 4; ++i) {
            ha[i] = hA2[lane + 32 * i];
            hb[i] = hB2[lane + 32 * i];
        }

#pragma unroll
        for (int b = 0; b < RPW / 4; ++b) {
            unsigned long long aA[4] = {0,0,0,0}, aB[4] = {0,0,0,0};
#pragma unroll
            for (int r = 0; r < 4; ++r) {
                const int j = 4 * b + r;
                ulonglong2 wv0, wv1, wv2, wv3;
                if (j < REG_ROWS) {
                    wv0 = wreg[j][0]; wv1 = wreg[j][1]; wv2 = wreg[j][2]; wv3 = wreg[j][3];
                } else if (j < REG_ROWS + SMEM_ROWS) {
                    const ulonglong2* wr = wsm2 + (size_t)(j - REG_ROWS) * (HH / 4);
                    wv0 = wr[lane]; wv1 = wr[lane + 32]; wv2 = wr[lane + 64]; wv3 = wr[lane + 96];
                } else {
                    const ulonglong2* wr = reinterpret_cast<const ulonglong2*>(
                        wrow0 + (size_t)j * HH);
                    wv0 = wr[lane]; wv1 = wr[lane + 32]; wv2 = wr[lane + 64]; wv3 = wr[lane + 96];
                }
                fma2(aA[r], wv0.x, ha[0].x); fma2(aA[r], wv0.y, ha[0].y);
                fma2(aA[r], wv1.x, ha[1].x); fma2(aA[r], wv1.y, ha[1].y);
                fma2(aA[r], wv2.x, ha[2].x); fma2(aA[r], wv2.y, ha[2].y);
                fma2(aA[r], wv3.x, ha[3].x); fma2(aA[r], wv3.y, ha[3].y);
                fma2(aB[r], wv0.x, hb[0].x); fma2(aB[r], wv0.y, hb[0].y);
                fma2(aB[r], wv1.x, hb[1].x); fma2(aB[r], wv1.y, hb[1].y);
                fma2(aB[r], wv2.x, hb[2].x); fma2(aB[r], wv2.y, hb[2].y);
                fma2(aB[r], wv3.x, hb[3].x); fma2(aB[r], wv3.y, hb[3].y);
            }
            reduce4_store(pack2(acc2_sum(aA[0]), acc2_sum(aB[0])),
                          pack2(acc2_sum(aA[1]), acc2_sum(aB[1])),
                          pack2(acc2_sum(aA[2]), acc2_sum(aB[2])),
                          pack2(acc2_sum(aA[3]), acc2_sum(aB[3])),
                          gates, ROWS, r_first + 4 * b, lane);
        }

        __syncthreads();   // gates complete (only CTA barrier per step)

        if (wid < 2) {
            const int sb = t & 1;
            float* stg = stage + sb * 2 * UPC + wid * UPC;
#pragma unroll
            for (int it = 0; it < UIT; ++it) {
                int u = lane + 32 * it;
                float g0 = gates[wid * ROWS + 0 * UPC + u] + gxv[it][0];
                float g1 = gates[wid * ROWS + 1 * UPC + u] + gxv[it][1];
                float g2 = gates[wid * ROWS + 2 * UPC + u] + gxv[it][2];
                float g3 = gates[wid * ROWS + 3 * UPC + u] + gxv[it][3];
                c_st[it] = sigf(g1) * c_st[it] + sigf(g0) * tanh_hw(g2);
                float hv = sigf(g3) * tanh_hw(c_st[it]);
                stg[u] = hv;
                if (t == TT - 1) g_h[0][dir][wid][ku + u] = hv;
            }
            __syncwarp();
            asm volatile("fence.proxy.async.shared::cta;" ::: "memory");
            if (lane < CSZ) {
                uint32_t src  = stage_a + ((t & 1) * 2 * UPC + wid * UPC) * 4;
                uint32_t ldst = hbuf_a[wb] + (wid * HH + ku) * 4;
                uint32_t rdst = mapa_u32(ldst, (uint32_t)lane);
                uint32_t rbar = mapa_u32(bar_a[bi], (uint32_t)lane);
                asm volatile(
                    "cp.async.bulk.shared::cluster.shared::cta.mbarrier::complete_tx::bytes "
                    "[%0], [%1], %2, [%3];"
                    :: "r"(rdst), "r"(src), "n"(CHUNK), "r"(rbar) : "memory");
            }
        }

        MBAR_WAIT_PARITY(bar_a[bi], (uint32_t)ph);
    }
}

// ---------------- phase 3: head ------------------------------------------------------
__global__ void head_kernel(const float* __restrict__ bi_w, const float* __restrict__ bi_b,
                            const float* __restrict__ blA, const float* __restrict__ blB,
                            const float* __restrict__ bl_b,
                            const float* __restrict__ out_w, const float* __restrict__ out_b,
                            float* __restrict__ out)
{
    __shared__ float hA[HH], hB[HH];
    __shared__ float red[16];
    const int j = threadIdx.x;
    const float w0 = bi_w[0], w1 = bi_w[1], bb = bi_b[0];

    hA[j] = w0 * g_h[0][0][0][j] + w1 * g_h[0][1][0][j] + bb;
    hB[j] = w0 * g_h[0][0][1][j] + w1 * g_h[0][1][1][j] + bb;
    __syncthreads();

    float acc = bl_b[j];
#pragma unroll 4
    for (int i = 0; i < HH; ++i)
        acc += hA[i] * blA[(size_t)i * HH + j] + hB[i] * blB[(size_t)i * HH + j];

    float v = tanhf(acc) * out_w[j];
#pragma unroll
    for (int off = 16; off; off >>= 1) v += __shfl_xor_sync(0xffffffffu, v, off);
    if ((j & 31) == 0) red[j >> 5] = v;
    __syncthreads();
    if (j < 16) {
        float r = red[j];
#pragma unroll
        for (int off = 8; off; off >>= 1) r += __shfl_xor_sync(0x0000ffffu, r, off);
        if (j == 0) out[0] = 1.f / (1.f + expf(-(r + out_b[0])));
    }
}

// ---------------- launch --------------------------------------------------------------
extern "C" void kernel_launch(void* const* d_in, const int* in_sizes, int n_in,
                              void* d_out, int out_size)
{
    (void)in_sizes; (void)n_in; (void)out_size;
    const int*   sentA = (const int*)d_in[0];
    const int*   sentB = (const int*)d_in[1];
    const float* emb   = (const float*)d_in[3];
    const float* w_ih  = (const float*)d_in[4];
    const float* w_hh  = (const float*)d_in[5];
    const float* b_ih  = (const float*)d_in[6];
    const float* b_hh  = (const float*)d_in[7];
    const float* bi_w  = (const float*)d_in[8];
    const float* bi_b  = (const float*)d_in[9];
    const float* blA   = (const float*)d_in[10];
    const float* blB   = (const float*)d_in[11];
    const float* bl_b  = (const float*)d_in[12];
    const float* out_w = (const float*)d_in[13];
    const float* out_b = (const float*)d_in[14];
    float* out = (float*)d_out;

    auto smem_for = [](int csz) {
        int upc = HH / csz, rows = 4 * upc;
        return (int)((16 * 6 * HH + 4 * HH + 2 * rows + 4 * upc) * sizeof(float)) + 16;
    };
    const int smem16 = smem_for(16);
    const int smem8  = smem_for(8);

    cudaFuncSetAttribute(lstm_fused_kernel<16>,
                         cudaFuncAttributeNonPortableClusterSizeAllowed, 1);
    cudaFuncSetAttribute(lstm_fused_kernel<16>,
                         cudaFuncAttributeMaxDynamicSharedMemorySize, smem16);
    cudaFuncSetAttribute(lstm_fused_kernel<8>,
                         cudaFuncAttributeMaxDynamicSharedMemorySize, smem8);

    cudaLaunchConfig_t cfg = {};
    cfg.blockDim = dim3(512, 1, 1);
    cfg.stream = 0;
    cudaLaunchAttribute attr[1];
    attr[0].id = cudaLaunchAttributeClusterDimension;
    cfg.attrs = attr;
    cfg.numAttrs = 1;

    cfg.gridDim = dim3(2 * 16, 1, 1);
    cfg.dynamicSmemBytes = smem16;
    attr[0].val.clusterDim.x = 16; attr[0].val.clusterDim.y = 1; attr[0].val.clusterDim.z = 1;

    int ncl = 0;
    cudaError_t e = cudaOccupancyMaxActiveClusters(&ncl, lstm_fused_kernel<16>, &cfg);
    if (e == cudaSuccess && ncl >= 3) {
        int use = ncl < 9 ? ncl : 9;
        int nworkers = (use - 2) * 16;
        cfg.gridDim = dim3(use * 16, 1, 1);
        init_kernel<<<1, 128>>>();
        cudaLaunchKernelEx(&cfg, lstm_fused_kernel<16>,
                           w_hh, sentA, sentB, emb, w_ih, b_ih, b_hh, 1, nworkers);
    } else {
        (void)cudaGetLastError();
        gemm_gx_kernel<<<dim3(32, 64, 2), 256>>>(sentA, sentB, emb, w_ih, b_ih, b_hh);
        if (e == cudaSuccess && ncl >= 1) {
            cfg.gridDim = dim3(2 * 16, 1, 1);
            cudaLaunchKernelEx(&cfg, lstm_fused_kernel<16>,
                               w_hh, sentA, sentB, emb, w_ih, b_ih, b_hh, 0, 0);
        } else {
            (void)cudaGetLastError();
            cfg.gridDim = dim3(2 * 8, 1, 1);
            cfg.dynamicSmemBytes = smem8;
            attr[0].val.clusterDim.x = 8;
            cudaLaunchKernelEx(&cfg, lstm_fused_kernel<8>,
                               w_hh, sentA, sentB, emb, w_ih, b_ih, b_hh, 0, 0);
        }
    }

    head_kernel<<<1, 512>>>(bi_w, bi_b, blA, blB, bl_b, out_w, out_b, out);
}

// round 16
// speedup vs baseline: 1.7136x; 1.2350x over previous
#include <cuda_runtime.h>
#include <cuda_bf16.h>
#include <cstdint>
#include <cstddef>

#define TT   2048
#define EE   300
#define HH   512

__device__ float g_gx[(size_t)4 * TT * 2048];   // [dir*2+sent][t][4H]
__device__ float g_h[2][2][2][HH];              // [parity][dir][sent][H]
__device__ int   g_tile_cnt[4][32];             // [dir*2+sent][stored t-tile] -> 32 when ready

__device__ __forceinline__ float sigf(float x) { return 1.f / (1.f + __expf(-x)); }
__device__ __forceinline__ float tanh_hw(float x) {
    float r;
    asm("tanh.approx.f32 %0, %1;" : "=f"(r) : "f"(x));
    return r;
}

__device__ __forceinline__ uint32_t smem_u32(const void* p) {
    uint32_t a;
    asm("{ .reg .u64 t; cvta.to.shared.u64 t, %1; cvt.u32.u64 %0, t; }" : "=r"(a) : "l"(p));
    return a;
}
__device__ __forceinline__ uint32_t mapa_u32(uint32_t addr, uint32_t rank) {
    uint32_t r;
    asm("mapa.shared::cluster.u32 %0, %1, %2;" : "=r"(r) : "r"(addr), "r"(rank));
    return r;
}
__device__ __forceinline__ void fma2(unsigned long long& acc,
                                     unsigned long long a, unsigned long long b) {
    asm("fma.rn.f32x2 %0, %1, %2, %0;" : "+l"(acc) : "l"(a), "l"(b));
}
__device__ __forceinline__ float acc2_sum(unsigned long long acc) {
    float lo, hi;
    asm("mov.b64 {%0, %1}, %2;" : "=f"(lo), "=f"(hi) : "l"(acc));
    return lo + hi;
}
__device__ __forceinline__ unsigned long long pack2(float a, float b) {
    unsigned long long r;
    asm("mov.b64 %0, {%1, %2};" : "=l"(r) : "f"(a), "f"(b));
    return r;
}
__device__ __forceinline__ void unpack2(unsigned long long v, float& a, float& b) {
    asm("mov.b64 {%0, %1}, %2;" : "=f"(a), "=f"(b) : "l"(v));
}
__device__ __forceinline__ void add2(unsigned long long& acc, unsigned long long v) {
    asm("add.rn.f32x2 %0, %0, %1;" : "+l"(acc) : "l"(v));
}
__device__ __forceinline__ int ld_acq_gpu(const int* p) {
    int v;
    asm volatile("ld.acquire.gpu.global.b32 %0, [%1];" : "=r"(v) : "l"(p) : "memory");
    return v;
}

// Reduce 4 packed pairs across the warp; lane 8j holds pair j fully reduced.
__device__ __forceinline__ unsigned long long reduce4_core(
    unsigned long long v0, unsigned long long v1,
    unsigned long long v2, unsigned long long v3, int lane)
{
    add2(v0, __shfl_xor_sync(0xffffffffu, v0, 16));
    add2(v1, __shfl_xor_sync(0xffffffffu, v1, 16));
    add2(v2, __shfl_xor_sync(0xffffffffu, v2, 16));
    add2(v3, __shfl_xor_sync(0xffffffffu, v3, 16));
    add2(v0, __shfl_xor_sync(0xffffffffu, v0, 8));
    add2(v1, __shfl_xor_sync(0xffffffffu, v1, 8));
    add2(v2, __shfl_xor_sync(0xffffffffu, v2, 8));
    add2(v3, __shfl_xor_sync(0xffffffffu, v3, 8));
    const int j = lane >> 3;
    unsigned long long val = v0;
    if (j == 1) val = v1;
    if (j == 2) val = v2;
    if (j == 3) val = v3;
    add2(val, __shfl_xor_sync(0xffffffffu, val, 4));
    add2(val, __shfl_xor_sync(0xffffffffu, val, 2));
    add2(val, __shfl_xor_sync(0xffffffffu, val, 1));
    return val;
}

// (A,B)-sentence variant: pair = (sumA_row, sumB_row); store into two gate banks.
__device__ __forceinline__ void reduce4_store(unsigned long long v0, unsigned long long v1,
                                              unsigned long long v2, unsigned long long v3,
                                              float* gates, int rows_c, int row0, int lane) {
    unsigned long long val = reduce4_core(v0, v1, v2, v3, lane);
    if ((lane & 7) == 0) {
        float fA, fB;
        unpack2(val, fA, fB);
        const int j = lane >> 3;
        gates[row0 + j] = fA;
        gates[rows_c + row0 + j] = fB;
    }
}

// row-pair variant: pair j = (sum_row(j), sum_row(j+4)); 8 rows in one pass.
__device__ __forceinline__ void reduce4_store_rows(unsigned long long v0, unsigned long long v1,
                                                   unsigned long long v2, unsigned long long v3,
                                                   float* gates, int row0, int lane) {
    unsigned long long val = reduce4_core(v0, v1, v2, v3, lane);
    if ((lane & 7) == 0) {
        float fA, fB;
        unpack2(val, fA, fB);
        const int j = lane >> 3;
        gates[row0 + j] = fA;
        gates[row0 + j + 4] = fB;
    }
}

#define MBAR_INIT(addr, cnt) \
    asm volatile("mbarrier.init.shared.b64 [%0], %1;" :: "r"(addr), "r"(cnt) : "memory")
#define MBAR_EXPECT_TX(addr, tx) \
    asm volatile("mbarrier.arrive.expect_tx.shared.b64 _, [%0], %1;" :: "r"(addr), "r"(tx) : "memory")
#define MBAR_WAIT_PARITY(addr, ph) do {                                              \
    uint32_t _m = (addr), _p = (ph), _d;                                             \
    asm volatile("{\n\t.reg .pred p;\n\t"                                            \
        "mbarrier.try_wait.parity.acquire.cta.shared::cta.b64 p, [%1], %2;\n\t"      \
        "selp.b32 %0, 1, 0, p;\n\t}"                                                 \
        : "=r"(_d) : "r"(_m), "r"(_p) : "memory");                                   \
    if (!_d) {                                                                        \
        asm volatile("{\n\t.reg .pred P1;\n\t"                                       \
            "WL_%=:\n\t"                                                              \
            "mbarrier.try_wait.parity.acquire.cta.shared::cta.b64 P1, [%0], %1, 0x989680;\n\t" \
            "@P1 bra.uni WD_%=;\n\t"                                                  \
            "bra.uni WL_%=;\n\t"                                                      \
            "WD_%=:\n\t}"                                                             \
            :: "r"(_m), "r"(_p) : "memory");                                          \
    }                                                                                 \
} while (0)

// ---------------- init: zero tile counters -----------------------------------------
__global__ void init_kernel() {
    int i = threadIdx.x;
    if (i < 128) ((int*)g_tile_cnt)[i] = 0;
}

// ---------------- standalone gx GEMM (fallback path), 256 threads ------------------
__global__ void gemm_gx_kernel(const int* __restrict__ sA, const int* __restrict__ sB,
                               const float* __restrict__ emb,
                               const float* __restrict__ w_ih,
                               const float* __restrict__ b_ih,
                               const float* __restrict__ b_hh)
{
    const int t0 = blockIdx.x * 64;
    const int r0 = blockIdx.y * 64;
    const int s  = blockIdx.z;
    const int* sent = s ? sB : sA;
    const int d = r0 >> 11;

    __shared__ float As[32][65];
    __shared__ float Bs[32][65];
    __shared__ int   toks[64];

    const int tid = threadIdx.x;
    const int ty = tid >> 4, tx = tid & 15;

    if (tid < 64) toks[tid] = sent[t0 + tid];
    __syncthreads();

    float acc[4][4] = {};

    for (int k0 = 0; k0 < EE; k0 += 32) {
#pragma unroll
        for (int m = 0; m < 8; ++m) {
            int idx = tid + m * 256;
            int tt = idx >> 5, kk = idx & 31;
            int k = k0 + kk;
            As[kk][tt] = (k < EE) ? emb[(size_t)toks[tt] * EE + k] : 0.f;
        }
#pragma unroll
        for (int m = 0; m < 8; ++m) {
            int idx = tid + m * 256;
            int rr = idx >> 5, kk = idx & 31;
            int k = k0 + kk;
            Bs[kk][rr] = (k < EE) ? w_ih[(size_t)(r0 + rr) * EE + k] : 0.f;
        }
        __syncthreads();
#pragma unroll
        for (int kk = 0; kk < 32; ++kk) {
            float a0 = As[kk][ty * 4 + 0], a1 = As[kk][ty * 4 + 1];
            float a2 = As[kk][ty * 4 + 2], a3 = As[kk][ty * 4 + 3];
            float b0 = Bs[kk][tx + 16 * 0], b1 = Bs[kk][tx + 16 * 1];
            float b2 = Bs[kk][tx + 16 * 2], b3 = Bs[kk][tx + 16 * 3];
            acc[0][0] += a0 * b0; acc[0][1] += a0 * b1; acc[0][2] += a0 * b2; acc[0][3] += a0 * b3;
            acc[1][0] += a1 * b0; acc[1][1] += a1 * b1; acc[1][2] += a1 * b2; acc[1][3] += a1 * b3;
            acc[2][0] += a2 * b0; acc[2][1] += a2 * b1; acc[2][2] += a2 * b2; acc[2][3] += a2 * b3;
            acc[3][0] += a3 * b0; acc[3][1] += a3 * b1; acc[3][2] += a3 * b2; acc[3][3] += a3 * b3;
        }
        __syncthreads();
    }

#pragma unroll
    for (int i = 0; i < 4; ++i) {
        int t = t0 + ty * 4 + i;
        int tstore = d ? (TT - 1 - t) : t;
        size_t rowbase = (((size_t)(d * 2 + s)) * TT + tstore) * 2048;
#pragma unroll
        for (int j = 0; j < 4; ++j) {
            int r = r0 + tx + 16 * j;
            g_gx[rowbase + (r & 2047)] = acc[i][j] + b_ih[r] + b_hh[r];
        }
    }
}

// ---------------- worker body: gx GEMM tiles with 512 threads ----------------------
__device__ void worker_body(int widx, int nwork, char* smem_raw,
                            const int* sA, const int* sB,
                            const float* emb, const float* w_ih,
                            const float* b_ih, const float* b_hh)
{
    float* As = reinterpret_cast<float*>(smem_raw);              // [32][65]
    float* Bs = As + 32 * 65;                                    // [32][65]
    int*   toks = reinterpret_cast<int*>(Bs + 32 * 65);          // [64]

    const int tid = threadIdx.x;
    const int ty = tid >> 4;          // 0..31 (2 t-rows each)
    const int tx = tid & 15;

    for (int i = widx; i < 4096; i += nwork) {
        const int stt = i >> 7;
        const int sub = i & 127;
        const int y   = sub >> 1;
        const int s   = sub & 1;
        const int d   = y >> 5;
        const int t0  = (d ? (31 - stt) : stt) << 6;
        const int r0  = y << 6;
        const int* sent = s ? sB : sA;

        if (tid < 64) toks[tid] = sent[t0 + tid];
        __syncthreads();

        float acc[2][4] = {};

        for (int k0 = 0; k0 < EE; k0 += 32) {
#pragma unroll
            for (int m = 0; m < 4; ++m) {
                int idx = tid + m * 512;
                int tt = idx >> 5, kk = idx & 31;
                int k = k0 + kk;
                As[kk * 65 + tt] = (k < EE) ? emb[(size_t)toks[tt] * EE + k] : 0.f;
            }
#pragma unroll
            for (int m = 0; m < 4; ++m) {
                int idx = tid + m * 512;
                int rr = idx >> 5, kk = idx & 31;
                int k = k0 + kk;
                Bs[kk * 65 + rr] = (k < EE) ? w_ih[(size_t)(r0 + rr) * EE + k] : 0.f;
            }
            __syncthreads();
#pragma unroll
            for (int kk = 0; kk < 32; ++kk) {
                float a0 = As[kk * 65 + ty * 2 + 0];
                float a1 = As[kk * 65 + ty * 2 + 1];
                float b0 = Bs[kk * 65 + tx + 16 * 0], b1 = Bs[kk * 65 + tx + 16 * 1];
                float b2 = Bs[kk * 65 + tx + 16 * 2], b3 = Bs[kk * 65 + tx + 16 * 3];
                acc[0][0] += a0 * b0; acc[0][1] += a0 * b1; acc[0][2] += a0 * b2; acc[0][3] += a0 * b3;
                acc[1][0] += a1 * b0; acc[1][1] += a1 * b1; acc[1][2] += a1 * b2; acc[1][3] += a1 * b3;
            }
            __syncthreads();
        }

#pragma unroll
        for (int ii = 0; ii < 2; ++ii) {
            int t = t0 + ty * 2 + ii;
            int tstore = d ? (TT - 1 - t) : t;
            size_t rowbase = (((size_t)(d * 2 + s)) * TT + tstore) * 2048;
#pragma unroll
            for (int j = 0; j < 4; ++j) {
                int r = r0 + tx + 16 * j;
                g_gx[rowbase + (r & 2047)] = acc[ii][j] + b_ih[r] + b_hh[r];
            }
        }
        __syncthreads();
        if (tid == 0) {
            __threadfence();
            atomicAdd(&g_tile_cnt[d * 2 + s][stt], 1);
        }
        __syncthreads();
    }
}

// ---------------- sentence-split fused kernel ---------------------------------------
// 4 LSTM clusters (dir x sentence) x CSZ CTAs; each CTA computes ONE sentence.
// Remaining CTAs are gemm workers.
template <int CSZ>
__global__ void __launch_bounds__(512, 1)
lstm_split_kernel(const float* __restrict__ w_hh,
                  const int* __restrict__ sA, const int* __restrict__ sB,
                  const float* __restrict__ emb, const float* __restrict__ w_ih,
                  const float* __restrict__ b_ih, const float* __restrict__ b_hh,
                  int wait_tiles, int n_worker_ctas)
{
    extern __shared__ float smf[];

    if (blockIdx.x >= 4 * CSZ) {
        worker_body(blockIdx.x - 4 * CSZ, n_worker_ctas, reinterpret_cast<char*>(smf),
                    sA, sB, emb, w_ih, b_ih, b_hh);
        return;
    }

    constexpr int NT   = 512;
    constexpr int NW   = 16;
    constexpr int UPC  = HH / CSZ;        // 32
    constexpr int ROWS = 4 * UPC;         // 128
    constexpr int RPW  = ROWS / NW;       // 8
    constexpr int REG_ROWS  = 2;
    constexpr int SMEM_ROWS = 6;
    constexpr int CHUNK = UPC * 4;        // 128 B
    constexpr uint32_t TX_TOTAL = HH * 4; // 2048 B

    float* w_sm  = smf;                                     // NW*SMEM_ROWS*HH
    float* h_s   = w_sm + NW * SMEM_ROWS * HH;              // [2][HH] parity
    float* gates = h_s + 2 * HH;                            // [ROWS]
    float* stage = gates + ROWS;                            // [2][UPC]
    unsigned long long* s_bar = reinterpret_cast<unsigned long long*>(stage + 2 * UPC);

    const int tid  = threadIdx.x;
    const int lane = tid & 31;
    const int wid  = tid >> 5;
    const int cl   = blockIdx.x / CSZ;    // 0..3
    const int dir  = cl >> 1;
    const int sent = cl & 1;
    const int rank = blockIdx.x % CSZ;
    const int ku   = rank * UPC;

    for (int i = tid; i < 2 * HH; i += NT) h_s[i] = 0.f;
    if (tid == 0) {
        MBAR_INIT(smem_u32(&s_bar[0]), 1);
        MBAR_INIT(smem_u32(&s_bar[1]), 1);
    }

    const float* wbase = w_hh + (size_t)dir * 2048 * HH;
    const int r_first = wid * RPW;
    const float* wrow0 = wbase + ((size_t)(r_first / UPC) * HH + ku + (r_first % UPC)) * HH;

    for (int j = 0; j < SMEM_ROWS; ++j) {
        const float4* src = reinterpret_cast<const float4*>(wrow0 + (size_t)(REG_ROWS + j) * HH);
        float4* dst = reinterpret_cast<float4*>(w_sm + (size_t)(wid * SMEM_ROWS + j) * HH);
        for (int i = lane; i < HH / 4; i += 32) dst[i] = src[i];
    }

    ulonglong2 wreg[REG_ROWS][4];
#pragma unroll
    for (int j = 0; j < REG_ROWS; ++j) {
        const ulonglong2* wr = reinterpret_cast<const ulonglong2*>(wrow0 + (size_t)j * HH);
#pragma unroll
        for (int i = 0; i < 4; ++i) wreg[j][i] = wr[lane + 32 * i];
    }

    __syncthreads();
    asm volatile("barrier.cluster.arrive.aligned;" ::: "memory");
    asm volatile("barrier.cluster.wait.aligned;"   ::: "memory");

    const uint32_t bar_a[2]  = { smem_u32(&s_bar[0]), smem_u32(&s_bar[1]) };
    const uint32_t hbuf_a[2] = { smem_u32(h_s), smem_u32(h_s + HH) };
    const uint32_t stage_a   = smem_u32(stage);

    const ulonglong2* wsm2 = reinterpret_cast<const ulonglong2*>(
        w_sm + (size_t)(wid * SMEM_ROWS) * HH);

    float c_st = 0.f;   // warp 0, lane = unit

    for (int t = 0; t < TT; ++t) {
        const int rb = t & 1;
        const int wb = (t + 1) & 1;
        const int bi = t & 1;
        const int ph = (t >> 1) & 1;
        const int sb = t & 1;

        if (wait_tiles && (t & 63) == 0) {
            const int* c0 = &g_tile_cnt[dir * 2 + sent][t >> 6];
            while (ld_acq_gpu(c0) < 32) {}
        }

        if (tid == 0) MBAR_EXPECT_TX(bar_a[bi], TX_TOTAL);

        // warp 0: gx for this CTA's 32 units (one sentence)
        float gxv[4];
        if (wid == 0) {
            const float* px = g_gx + ((size_t)(dir * 2 + sent) * TT + t) * 2048 + ku + lane;
#pragma unroll
            for (int g = 0; g < 4; ++g) gxv[g] = __ldg(px + g * HH);
        }

        // h into registers (single sentence)
        const ulonglong2* h2 = reinterpret_cast<const ulonglong2*>(h_s + rb * HH);
        ulonglong2 ha[4];
#pragma unroll
        for (int i = 0; i < 4; ++i) ha[i] = h2[lane + 32 * i];

        // matvec: 8 rows, one sentence
        unsigned long long a8[RPW];
#pragma unroll
        for (int j = 0; j < RPW; ++j) a8[j] = 0ull;
#pragma unroll
        for (int j = 0; j < RPW; ++j) {
            ulonglong2 wv0, wv1, wv2, wv3;
            if (j < REG_ROWS) {
                wv0 = wreg[j][0]; wv1 = wreg[j][1]; wv2 = wreg[j][2]; wv3 = wreg[j][3];
            } else {
                const ulonglong2* wr = wsm2 + (size_t)(j - REG_ROWS) * (HH / 4);
                wv0 = wr[lane]; wv1 = wr[lane + 32]; wv2 = wr[lane + 64]; wv3 = wr[lane + 96];
            }
            fma2(a8[j], wv0.x, ha[0].x); fma2(a8[j], wv0.y, ha[0].y);
            fma2(a8[j], wv1.x, ha[1].x); fma2(a8[j], wv1.y, ha[1].y);
            fma2(a8[j], wv2.x, ha[2].x); fma2(a8[j], wv2.y, ha[2].y);
            fma2(a8[j], wv3.x, ha[3].x); fma2(a8[j], wv3.y, ha[3].y);
        }
        float s8[RPW];
#pragma unroll
        for (int j = 0; j < RPW; ++j) s8[j] = acc2_sum(a8[j]);
        // one reduction pass: pairs (j, j+4)
        reduce4_store_rows(pack2(s8[0], s8[4]), pack2(s8[1], s8[5]),
                           pack2(s8[2], s8[6]), pack2(s8[3], s8[7]),
                           gates, r_first, lane);

        __syncthreads();   // gates complete

        // warp 0 tail: pointwise for all 32 units + 16 DSMEM copies
        if (wid == 0) {
            const int u = lane;
            float g0 = gates[0 * UPC + u] + gxv[0];
            float g1 = gates[1 * UPC + u] + gxv[1];
            float g2 = gates[2 * UPC + u] + gxv[2];
            float g3 = gates[3 * UPC + u] + gxv[3];
            c_st = sigf(g1) * c_st + sigf(g0) * tanh_hw(g2);
            float hv = sigf(g3) * tanh_hw(c_st);
            stage[sb * UPC + u] = hv;
            if (t == TT - 1) g_h[0][dir][sent][ku + u] = hv;
            __syncwarp();
            asm volatile("fence.proxy.async.shared::cta;" ::: "memory");
            if (lane < CSZ) {
                uint32_t src  = stage_a + (sb * UPC) * 4;
                uint32_t ldst = hbuf_a[wb] + ku * 4;
                uint32_t rdst = mapa_u32(ldst, (uint32_t)lane);
                uint32_t rbar = mapa_u32(bar_a[bi], (uint32_t)lane);
                asm volatile(
                    "cp.async.bulk.shared::cluster.shared::cta.mbarrier::complete_tx::bytes "
                    "[%0], [%1], %2, [%3];"
                    :: "r"(rdst), "r"(src), "n"(CHUNK), "r"(rbar) : "memory");
            }
        }

        MBAR_WAIT_PARITY(bar_a[bi], (uint32_t)ph);
    }
}

// ---------------- combined fused kernel (R15, fallback) ----------------------------
template <int CSZ>
__global__ void __launch_bounds__(512, 1)
lstm_fused_kernel(const float* __restrict__ w_hh,
                  const int* __restrict__ sA, const int* __restrict__ sB,
                  const float* __restrict__ emb, const float* __restrict__ w_ih,
                  const float* __restrict__ b_ih, const float* __restrict__ b_hh,
                  int wait_tiles, int n_worker_ctas)
{
    extern __shared__ float smf[];

    if (blockIdx.x >= 2 * CSZ) {
        worker_body(blockIdx.x - 2 * CSZ, n_worker_ctas, reinterpret_cast<char*>(smf),
                    sA, sB, emb, w_ih, b_ih, b_hh);
        return;
    }

    constexpr int NT   = 512;
    constexpr int NW   = 16;
    constexpr int UPC  = HH / CSZ;
    constexpr int ROWS = 4 * UPC;
    constexpr int RPW  = ROWS / NW;
    constexpr int REG_ROWS  = 2;
    constexpr int SMEM_ROWS = 6;
    constexpr int UIT  = UPC / 32;
    constexpr int CHUNK = UPC * 4;
    constexpr uint32_t TX_TOTAL = 2 * HH * 4;

    float* w_sm  = smf;
    float* h_s   = w_sm + NW * SMEM_ROWS * HH;
    float* gates = h_s + 4 * HH;
    float* stage = gates + 2 * ROWS;
    unsigned long long* s_bar = reinterpret_cast<unsigned long long*>(stage + 4 * UPC);

    const int tid  = threadIdx.x;
    const int lane = tid & 31;
    const int wid  = tid >> 5;
    const int dir  = blockIdx.x / CSZ;
    const int rank = blockIdx.x % CSZ;
    const int ku   = rank * UPC;

    for (int i = tid; i < 2 * HH; i += NT) h_s[i] = 0.f;
    if (tid == 0) {
        MBAR_INIT(smem_u32(&s_bar[0]), 1);
        MBAR_INIT(smem_u32(&s_bar[1]), 1);
    }

    const float* wbase = w_hh + (size_t)dir * 2048 * HH;
    const int r_first = wid * RPW;
    const float* wrow0 = wbase + ((size_t)(r_first / UPC) * HH + ku + (r_first % UPC)) * HH;

    for (int j = 0; j < SMEM_ROWS; ++j) {
        const float4* src = reinterpret_cast<const float4*>(wrow0 + (size_t)(REG_ROWS + j) * HH);
        float4* dst = reinterpret_cast<float4*>(w_sm + (size_t)(wid * SMEM_ROWS + j) * HH);
        for (int i = lane; i < HH / 4; i += 32) dst[i] = src[i];
    }

    ulonglong2 wreg[REG_ROWS][4];
#pragma unroll
    for (int j = 0; j < REG_ROWS; ++j) {
        const ulonglong2* wr = reinterpret_cast<const ulonglong2*>(wrow0 + (size_t)j * HH);
#pragma unroll
        for (int i = 0; i < 4; ++i) wreg[j][i] = wr[lane + 32 * i];
    }

    __syncthreads();
    asm volatile("barrier.cluster.arrive.aligned;" ::: "memory");
    asm volatile("barrier.cluster.wait.aligned;"   ::: "memory");

    const uint32_t bar_a[2]  = { smem_u32(&s_bar[0]), smem_u32(&s_bar[1]) };
    const uint32_t hbuf_a[2] = { smem_u32(h_s), smem_u32(h_s + 2 * HH) };
    const uint32_t stage_a   = smem_u32(stage);

    const ulonglong2* wsm2 = reinterpret_cast<const ulonglong2*>(
        w_sm + (size_t)(wid * SMEM_ROWS) * HH);

    float c_st[UIT];
#pragma unroll
    for (int i = 0; i < UIT; ++i) c_st[i] = 0.f;

    for (int t = 0; t < TT; ++t) {
        const int rb = t & 1;
        const int wb = (t + 1) & 1;
        const int bi = t & 1;
        const int ph = (t >> 1) & 1;

        if (wait_tiles && (t & 63) == 0) {
            const int tt = t >> 6;
            const int* c0 = &g_tile_cnt[dir * 2 + 0][tt];
            const int* c1 = &g_tile_cnt[dir * 2 + 1][tt];
            while (ld_acq_gpu(c0) < 32) {}
            while (ld_acq_gpu(c1) < 32) {}
        }

        if (tid == 0) MBAR_EXPECT_TX(bar_a[bi], TX_TOTAL);

        float gxv[UIT][4];
        if (wid < 2) {
            const float* px = g_gx + ((size_t)(dir * 2 + wid) * TT + t) * 2048 + ku;
#pragma unroll
            for (int it = 0; it < UIT; ++it) {
                int u = lane + 32 * it;
#pragma unroll
                for (int g = 0; g < 4; ++g) gxv[it][g] = __ldg(px + g * HH + u);
            }
        }

        const ulonglong2* hA2 = reinterpret_cast<const ulonglong2*>(h_s + rb * 2 * HH);
        const ulonglong2* hB2 = reinterpret_cast<const ulonglong2*>(h_s + rb * 2 * HH + HH);
        ulonglong2 ha[4], hb[4];
#pragma unroll
        for (int i = 0; i < 4; ++i) {
            ha[i] = hA2[lane + 32 * i];
            hb[i] = hB2[lane + 32 * i];
        }

#pragma unroll
        for (int b = 0; b < RPW / 4; ++b) {
            unsigned long long aA[4] = {0,0,0,0}, aB[4] = {0,0,0,0};
#pragma unroll
            for (int r = 0; r < 4; ++r) {
                const int j = 4 * b + r;
                ulonglong2 wv0, wv1, wv2, wv3;
                if (j < REG_ROWS) {
                    wv0 = wreg[j][0]; wv1 = wreg[j][1]; wv2 = wreg[j][2]; wv3 = wreg[j][3];
                } else {
                    const ulonglong2* wr = wsm2 + (size_t)(j - REG_ROWS) * (HH / 4);
                    wv0 = wr[lane]; wv1 = wr[lane + 32]; wv2 = wr[lane + 64]; wv3 = wr[lane + 96];
                }
                fma2(aA[r], wv0.x, ha[0].x); fma2(aA[r], wv0.y, ha[0].y);
                fma2(aA[r], wv1.x, ha[1].x); fma2(aA[r], wv1.y, ha[1].y);
                fma2(aA[r], wv2.x, ha[2].x); fma2(aA[r], wv2.y, ha[2].y);
                fma2(aA[r], wv3.x, ha[3].x); fma2(aA[r], wv3.y, ha[3].y);
                fma2(aB[r], wv0.x, hb[0].x); fma2(aB[r], wv0.y, hb[0].y);
                fma2(aB[r], wv1.x, hb[1].x); fma2(aB[r], wv1.y, hb[1].y);
                fma2(aB[r], wv2.x, hb[2].x); fma2(aB[r], wv2.y, hb[2].y);
                fma2(aB[r], wv3.x, hb[3].x); fma2(aB[r], wv3.y, hb[3].y);
            }
            reduce4_store(pack2(acc2_sum(aA[0]), acc2_sum(aB[0])),
                          pack2(acc2_sum(aA[1]), acc2_sum(aB[1])),
                          pack2(acc2_sum(aA[2]), acc2_sum(aB[2])),
                          pack2(acc2_sum(aA[3]), acc2_sum(aB[3])),
                          gates, ROWS, r_first + 4 * b, lane);
        }

        __syncthreads();

        if (wid < 2) {
            const int sb = t & 1;
            float* stg = stage + sb * 2 * UPC + wid * UPC;
#pragma unroll
            for (int it = 0; it < UIT; ++it) {
                int u = lane + 32 * it;
                float g0 = gates[wid * ROWS + 0 * UPC + u] + gxv[it][0];
                float g1 = gates[wid * ROWS + 1 * UPC + u] + gxv[it][1];
                float g2 = gates[wid * ROWS + 2 * UPC + u] + gxv[it][2];
                float g3 = gates[wid * ROWS + 3 * UPC + u] + gxv[it][3];
                c_st[it] = sigf(g1) * c_st[it] + sigf(g0) * tanh_hw(g2);
                float hv = sigf(g3) * tanh_hw(c_st[it]);
                stg[u] = hv;
                if (t == TT - 1) g_h[0][dir][wid][ku + u] = hv;
            }
            __syncwarp();
            asm volatile("fence.proxy.async.shared::cta;" ::: "memory");
            if (lane < CSZ) {
                uint32_t src  = stage_a + ((t & 1) * 2 * UPC + wid * UPC) * 4;
                uint32_t ldst = hbuf_a[wb] + (wid * HH + ku) * 4;
                uint32_t rdst = mapa_u32(ldst, (uint32_t)lane);
                uint32_t rbar = mapa_u32(bar_a[bi], (uint32_t)lane);
                asm volatile(
                    "cp.async.bulk.shared::cluster.shared::cta.mbarrier::complete_tx::bytes "
                    "[%0], [%1], %2, [%3];"
                    :: "r"(rdst), "r"(src), "n"(CHUNK), "r"(rbar) : "memory");
            }
        }

        MBAR_WAIT_PARITY(bar_a[bi], (uint32_t)ph);
    }
}

// ---------------- phase 3: head ------------------------------------------------------
__global__ void head_kernel(const float* __restrict__ bi_w, const float* __restrict__ bi_b,
                            const float* __restrict__ blA, const float* __restrict__ blB,
                            const float* __restrict__ bl_b,
                            const float* __restrict__ out_w, const float* __restrict__ out_b,
                            float* __restrict__ out)
{
    __shared__ float hA[HH], hB[HH];
    __shared__ float red[16];
    const int j = threadIdx.x;
    const float w0 = bi_w[0], w1 = bi_w[1], bb = bi_b[0];

    hA[j] = w0 * g_h[0][0][0][j] + w1 * g_h[0][1][0][j] + bb;
    hB[j] = w0 * g_h[0][0][1][j] + w1 * g_h[0][1][1][j] + bb;
    __syncthreads();

    float acc = bl_b[j];
#pragma unroll 4
    for (int i = 0; i < HH; ++i)
        acc += hA[i] * blA[(size_t)i * HH + j] + hB[i] * blB[(size_t)i * HH + j];

    float v = tanhf(acc) * out_w[j];
#pragma unroll
    for (int off = 16; off; off >>= 1) v += __shfl_xor_sync(0xffffffffu, v, off);
    if ((j & 31) == 0) red[j >> 5] = v;
    __syncthreads();
    if (j < 16) {
        float r = red[j];
#pragma unroll
        for (int off = 8; off; off >>= 1) r += __shfl_xor_sync(0x0000ffffu, r, off);
        if (j == 0) out[0] = 1.f / (1.f + expf(-(r + out_b[0])));
    }
}

// ---------------- launch --------------------------------------------------------------
extern "C" void kernel_launch(void* const* d_in, const int* in_sizes, int n_in,
                              void* d_out, int out_size)
{
    (void)in_sizes; (void)n_in; (void)out_size;
    const int*   sentA = (const int*)d_in[0];
    const int*   sentB = (const int*)d_in[1];
    const float* emb   = (const float*)d_in[3];
    const float* w_ih  = (const float*)d_in[4];
    const float* w_hh  = (const float*)d_in[5];
    const float* b_ih  = (const float*)d_in[6];
    const float* b_hh  = (const float*)d_in[7];
    const float* bi_w  = (const float*)d_in[8];
    const float* bi_b  = (const float*)d_in[9];
    const float* blA   = (const float*)d_in[10];
    const float* blB   = (const float*)d_in[11];
    const float* bl_b  = (const float*)d_in[12];
    const float* out_w = (const float*)d_in[13];
    const float* out_b = (const float*)d_in[14];
    float* out = (float*)d_out;

    const int smem_split = (int)((16 * 6 * HH + 2 * HH + 4 * (HH / 16) + 2 * (HH / 16) + 128) * sizeof(float)) + 16;
    const int smem_comb  = (int)((16 * 6 * HH + 4 * HH + 2 * 4 * (HH / 16) + 4 * (HH / 16)) * sizeof(float)) + 16;

    cudaFuncSetAttribute(lstm_split_kernel<16>,
                         cudaFuncAttributeNonPortableClusterSizeAllowed, 1);
    cudaFuncSetAttribute(lstm_split_kernel<16>,
                         cudaFuncAttributeMaxDynamicSharedMemorySize, smem_split);
    cudaFuncSetAttribute(lstm_fused_kernel<16>,
                         cudaFuncAttributeNonPortableClusterSizeAllowed, 1);
    cudaFuncSetAttribute(lstm_fused_kernel<16>,
                         cudaFuncAttributeMaxDynamicSharedMemorySize, smem_comb);

    cudaLaunchConfig_t cfg = {};
    cfg.blockDim = dim3(512, 1, 1);
    cfg.stream = 0;
    cudaLaunchAttribute attr[1];
    attr[0].id = cudaLaunchAttributeClusterDimension;
    attr[0].val.clusterDim.x = 16; attr[0].val.clusterDim.y = 1; attr[0].val.clusterDim.z = 1;
    cfg.attrs = attr;
    cfg.numAttrs = 1;

    // query split occupancy
    cfg.gridDim = dim3(4 * 16, 1, 1);
    cfg.dynamicSmemBytes = smem_split;
    int ncl_split = 0;
    cudaError_t es = cudaOccupancyMaxActiveClusters(&ncl_split, lstm_split_kernel<16>, &cfg);
    if (es != cudaSuccess) { ncl_split = 0; (void)cudaGetLastError(); }

    if (ncl_split >= 5) {
        int use = ncl_split < 9 ? ncl_split : 9;
        int nworkers = (use - 4) * 16;
        cfg.gridDim = dim3(use * 16, 1, 1);
        cfg.dynamicSmemBytes = smem_split;
        init_kernel<<<1, 128>>>();
        cudaLaunchKernelEx(&cfg, lstm_split_kernel<16>,
                           w_hh, sentA, sentB, emb, w_ih, b_ih, b_hh, 1, nworkers);
    } else if (ncl_split == 4) {
        gemm_gx_kernel<<<dim3(32, 64, 2), 256>>>(sentA, sentB, emb, w_ih, b_ih, b_hh);
        cfg.gridDim = dim3(4 * 16, 1, 1);
        cfg.dynamicSmemBytes = smem_split;
        cudaLaunchKernelEx(&cfg, lstm_split_kernel<16>,
                           w_hh, sentA, sentB, emb, w_ih, b_ih, b_hh, 0, 0);
    } else {
        // fallback: combined 2-cluster path (R15)
        cfg.gridDim = dim3(2 * 16, 1, 1);
        cfg.dynamicSmemBytes = smem_comb;
        int ncl = 0;
        cudaError_t e = cudaOccupancyMaxActiveClusters(&ncl, lstm_fused_kernel<16>, &cfg);
        if (e == cudaSuccess && ncl >= 3) {
            int use = ncl < 9 ? ncl : 9;
            int nworkers = (use - 2) * 16;
            cfg.gridDim = dim3(use * 16, 1, 1);
            init_kernel<<<1, 128>>>();
            cudaLaunchKernelEx(&cfg, lstm_fused_kernel<16>,
                               w_hh, sentA, sentB, emb, w_ih, b_ih, b_hh, 1, nworkers);
        } else {
            (void)cudaGetLastError();
            gemm_gx_kernel<<<dim3(32, 64, 2), 256>>>(sentA, sentB, emb, w_ih, b_ih, b_hh);
            cfg.gridDim = dim3(2 * 16, 1, 1);
            cudaLaunchKernelEx(&cfg, lstm_fused_kernel<16>,
                               w_hh, sentA, sentB, emb, w_ih, b_ih, b_hh, 0, 0);
        }
    }

    head_kernel<<<1, 512>>>(bi_w, bi_b, blA, blB, bl_b, out_w, out_b, out);
}

// round 17
// speedup vs baseline: 1.8263x; 1.0658x over previous
#include <cuda_runtime.h>
#include <cuda_bf16.h>
#include <cstdint>
#include <cstddef>

#define TT   2048
#define EE   300
#define HH   512

__device__ float g_gx[(size_t)4 * TT * 2048];   // [dir*2+sent][t][4H]
__device__ float g_h[2][2][2][HH];              // [parity][dir][sent][H]
__device__ int   g_tile_cnt[4][32];             // [dir*2+sent][stored t-tile] -> 32 when ready

__device__ __forceinline__ float sigf(float x) { return 1.f / (1.f + __expf(-x)); }
__device__ __forceinline__ float tanh_hw(float x) {
    float r;
    asm("tanh.approx.f32 %0, %1;" : "=f"(r) : "f"(x));
    return r;
}

__device__ __forceinline__ uint32_t smem_u32(const void* p) {
    uint32_t a;
    asm("{ .reg .u64 t; cvta.to.shared.u64 t, %1; cvt.u32.u64 %0, t; }" : "=r"(a) : "l"(p));
    return a;
}
__device__ __forceinline__ uint32_t mapa_u32(uint32_t addr, uint32_t rank) {
    uint32_t r;
    asm("mapa.shared::cluster.u32 %0, %1, %2;" : "=r"(r) : "r"(addr), "r"(rank));
    return r;
}
__device__ __forceinline__ void fma2(unsigned long long& acc,
                                     unsigned long long a, unsigned long long b) {
    asm("fma.rn.f32x2 %0, %1, %2, %0;" : "+l"(acc) : "l"(a), "l"(b));
}
__device__ __forceinline__ float acc2_sum(unsigned long long acc) {
    float lo, hi;
    asm("mov.b64 {%0, %1}, %2;" : "=f"(lo), "=f"(hi) : "l"(acc));
    return lo + hi;
}
__device__ __forceinline__ unsigned long long pack2(float a, float b) {
    unsigned long long r;
    asm("mov.b64 %0, {%1, %2};" : "=l"(r) : "f"(a), "f"(b));
    return r;
}
__device__ __forceinline__ void unpack2(unsigned long long v, float& a, float& b) {
    asm("mov.b64 {%0, %1}, %2;" : "=f"(a), "=f"(b) : "l"(v));
}
__device__ __forceinline__ void add2(unsigned long long& acc, unsigned long long v) {
    asm("add.rn.f32x2 %0, %0, %1;" : "+l"(acc) : "l"(v));
}
__device__ __forceinline__ int ld_acq_gpu(const int* p) {
    int v;
    asm volatile("ld.acquire.gpu.global.b32 %0, [%1];" : "=r"(v) : "l"(p) : "memory");
    return v;
}

// Reduce 4 packed pairs across the warp; lane 8j holds pair j fully reduced.
__device__ __forceinline__ unsigned long long reduce4_core(
    unsigned long long v0, unsigned long long v1,
    unsigned long long v2, unsigned long long v3, int lane)
{
    add2(v0, __shfl_xor_sync(0xffffffffu, v0, 16));
    add2(v1, __shfl_xor_sync(0xffffffffu, v1, 16));
    add2(v2, __shfl_xor_sync(0xffffffffu, v2, 16));
    add2(v3, __shfl_xor_sync(0xffffffffu, v3, 16));
    add2(v0, __shfl_xor_sync(0xffffffffu, v0, 8));
    add2(v1, __shfl_xor_sync(0xffffffffu, v1, 8));
    add2(v2, __shfl_xor_sync(0xffffffffu, v2, 8));
    add2(v3, __shfl_xor_sync(0xffffffffu, v3, 8));
    const int j = lane >> 3;
    unsigned long long val = v0;
    if (j == 1) val = v1;
    if (j == 2) val = v2;
    if (j == 3) val = v3;
    add2(val, __shfl_xor_sync(0xffffffffu, val, 4));
    add2(val, __shfl_xor_sync(0xffffffffu, val, 2));
    add2(val, __shfl_xor_sync(0xffffffffu, val, 1));
    return val;
}

__device__ __forceinline__ void reduce4_store(unsigned long long v0, unsigned long long v1,
                                              unsigned long long v2, unsigned long long v3,
                                              float* gates, int rows_c, int row0, int lane) {
    unsigned long long val = reduce4_core(v0, v1, v2, v3, lane);
    if ((lane & 7) == 0) {
        float fA, fB;
        unpack2(val, fA, fB);
        const int j = lane >> 3;
        gates[row0 + j] = fA;
        gates[rows_c + row0 + j] = fB;
    }
}

__device__ __forceinline__ void reduce4_store_rows(unsigned long long v0, unsigned long long v1,
                                                   unsigned long long v2, unsigned long long v3,
                                                   float* gates, int row0, int lane) {
    unsigned long long val = reduce4_core(v0, v1, v2, v3, lane);
    if ((lane & 7) == 0) {
        float fA, fB;
        unpack2(val, fA, fB);
        const int j = lane >> 3;
        gates[row0 + j] = fA;
        gates[row0 + j + 4] = fB;
    }
}

#define MBAR_INIT(addr, cnt) \
    asm volatile("mbarrier.init.shared.b64 [%0], %1;" :: "r"(addr), "r"(cnt) : "memory")
#define MBAR_EXPECT_TX(addr, tx) \
    asm volatile("mbarrier.arrive.expect_tx.shared.b64 _, [%0], %1;" :: "r"(addr), "r"(tx) : "memory")
#define MBAR_WAIT_PARITY(addr, ph) do {                                              \
    uint32_t _m = (addr), _p = (ph), _d;                                             \
    asm volatile("{\n\t.reg .pred p;\n\t"                                            \
        "mbarrier.try_wait.parity.acquire.cta.shared::cta.b64 p, [%1], %2;\n\t"      \
        "selp.b32 %0, 1, 0, p;\n\t}"                                                 \
        : "=r"(_d) : "r"(_m), "r"(_p) : "memory");                                   \
    if (!_d) {                                                                        \
        asm volatile("{\n\t.reg .pred P1;\n\t"                                       \
            "WL_%=:\n\t"                                                              \
            "mbarrier.try_wait.parity.acquire.cta.shared::cta.b64 P1, [%0], %1, 0x989680;\n\t" \
            "@P1 bra.uni WD_%=;\n\t"                                                  \
            "bra.uni WL_%=;\n\t"                                                      \
            "WD_%=:\n\t}"                                                             \
            :: "r"(_m), "r"(_p) : "memory");                                          \
    }                                                                                 \
} while (0)

// ---------------- init: zero tile counters -----------------------------------------
__global__ void init_kernel() {
    int i = threadIdx.x;
    if (i < 128) ((int*)g_tile_cnt)[i] = 0;
}

// ---------------- standalone gx GEMM (fallback path), 256 threads ------------------
__global__ void gemm_gx_kernel(const int* __restrict__ sA, const int* __restrict__ sB,
                               const float* __restrict__ emb,
                               const float* __restrict__ w_ih,
                               const float* __restrict__ b_ih,
                               const float* __restrict__ b_hh)
{
    const int t0 = blockIdx.x * 64;
    const int r0 = blockIdx.y * 64;
    const int s  = blockIdx.z;
    const int* sent = s ? sB : sA;
    const int d = r0 >> 11;

    __shared__ float As[32][65];
    __shared__ float Bs[32][65];
    __shared__ int   toks[64];

    const int tid = threadIdx.x;
    const int ty = tid >> 4, tx = tid & 15;

    if (tid < 64) toks[tid] = sent[t0 + tid];
    __syncthreads();

    float acc[4][4] = {};

    for (int k0 = 0; k0 < EE; k0 += 32) {
#pragma unroll
        for (int m = 0; m < 8; ++m) {
            int idx = tid + m * 256;
            int tt = idx >> 5, kk = idx & 31;
            int k = k0 + kk;
            As[kk][tt] = (k < EE) ? emb[(size_t)toks[tt] * EE + k] : 0.f;
        }
#pragma unroll
        for (int m = 0; m < 8; ++m) {
            int idx = tid + m * 256;
            int rr = idx >> 5, kk = idx & 31;
            int k = k0 + kk;
            Bs[kk][rr] = (k < EE) ? w_ih[(size_t)(r0 + rr) * EE + k] : 0.f;
        }
        __syncthreads();
#pragma unroll
        for (int kk = 0; kk < 32; ++kk) {
            float a0 = As[kk][ty * 4 + 0], a1 = As[kk][ty * 4 + 1];
            float a2 = As[kk][ty * 4 + 2], a3 = As[kk][ty * 4 + 3];
            float b0 = Bs[kk][tx + 16 * 0], b1 = Bs[kk][tx + 16 * 1];
            float b2 = Bs[kk][tx + 16 * 2], b3 = Bs[kk][tx + 16 * 3];
            acc[0][0] += a0 * b0; acc[0][1] += a0 * b1; acc[0][2] += a0 * b2; acc[0][3] += a0 * b3;
            acc[1][0] += a1 * b0; acc[1][1] += a1 * b1; acc[1][2] += a1 * b2; acc[1][3] += a1 * b3;
            acc[2][0] += a2 * b0; acc[2][1] += a2 * b1; acc[2][2] += a2 * b2; acc[2][3] += a2 * b3;
            acc[3][0] += a3 * b0; acc[3][1] += a3 * b1; acc[3][2] += a3 * b2; acc[3][3] += a3 * b3;
        }
        __syncthreads();
    }

#pragma unroll
    for (int i = 0; i < 4; ++i) {
        int t = t0 + ty * 4 + i;
        int tstore = d ? (TT - 1 - t) : t;
        size_t rowbase = (((size_t)(d * 2 + s)) * TT + tstore) * 2048;
#pragma unroll
        for (int j = 0; j < 4; ++j) {
            int r = r0 + tx + 16 * j;
            g_gx[rowbase + (r & 2047)] = acc[i][j] + b_ih[r] + b_hh[r];
        }
    }
}

// ---------------- worker body: gx GEMM tiles with 512 threads ----------------------
__device__ void worker_body(int widx, int nwork, char* smem_raw,
                            const int* sA, const int* sB,
                            const float* emb, const float* w_ih,
                            const float* b_ih, const float* b_hh)
{
    float* As = reinterpret_cast<float*>(smem_raw);              // [32][65]
    float* Bs = As + 32 * 65;                                    // [32][65]
    int*   toks = reinterpret_cast<int*>(Bs + 32 * 65);          // [64]

    const int tid = threadIdx.x;
    const int ty = tid >> 4;          // 0..31 (2 t-rows each)
    const int tx = tid & 15;

    for (int i = widx; i < 4096; i += nwork) {
        const int stt = i >> 7;
        const int sub = i & 127;
        const int y   = sub >> 1;
        const int s   = sub & 1;
        const int d   = y >> 5;
        const int t0  = (d ? (31 - stt) : stt) << 6;
        const int r0  = y << 6;
        const int* sent = s ? sB : sA;

        if (tid < 64) toks[tid] = sent[t0 + tid];
        __syncthreads();

        float acc[2][4] = {};

        for (int k0 = 0; k0 < EE; k0 += 32) {
#pragma unroll
            for (int m = 0; m < 4; ++m) {
                int idx = tid + m * 512;
                int tt = idx >> 5, kk = idx & 31;
                int k = k0 + kk;
                As[kk * 65 + tt] = (k < EE) ? emb[(size_t)toks[tt] * EE + k] : 0.f;
            }
#pragma unroll
            for (int m = 0; m < 4; ++m) {
                int idx = tid + m * 512;
                int rr = idx >> 5, kk = idx & 31;
                int k = k0 + kk;
                Bs[kk * 65 + rr] = (k < EE) ? w_ih[(size_t)(r0 + rr) * EE + k] : 0.f;
            }
            __syncthreads();
#pragma unroll
            for (int kk = 0; kk < 32; ++kk) {
                float a0 = As[kk * 65 + ty * 2 + 0];
                float a1 = As[kk * 65 + ty * 2 + 1];
                float b0 = Bs[kk * 65 + tx + 16 * 0], b1 = Bs[kk * 65 + tx + 16 * 1];
                float b2 = Bs[kk * 65 + tx + 16 * 2], b3 = Bs[kk * 65 + tx + 16 * 3];
                acc[0][0] += a0 * b0; acc[0][1] += a0 * b1; acc[0][2] += a0 * b2; acc[0][3] += a0 * b3;
                acc[1][0] += a1 * b0; acc[1][1] += a1 * b1; acc[1][2] += a1 * b2; acc[1][3] += a1 * b3;
            }
            __syncthreads();
        }

#pragma unroll
        for (int ii = 0; ii < 2; ++ii) {
            int t = t0 + ty * 2 + ii;
            int tstore = d ? (TT - 1 - t) : t;
            size_t rowbase = (((size_t)(d * 2 + s)) * TT + tstore) * 2048;
#pragma unroll
            for (int j = 0; j < 4; ++j) {
                int r = r0 + tx + 16 * j;
                g_gx[rowbase + (r & 2047)] = acc[ii][j] + b_ih[r] + b_hh[r];
            }
        }
        __syncthreads();
        if (tid == 0) {
            __threadfence();
            atomicAdd(&g_tile_cnt[d * 2 + s][stt], 1);
        }
        __syncthreads();
    }
}

// ---------------- sentence-split fused kernel ---------------------------------------
// 4 LSTM clusters (dir x sentence) x CSZ CTAs; each CTA computes ONE sentence.
// REG_ROWS=3 / SMEM_ROWS=5 (single-sentence register headroom allows one more
// register-resident weight row: -32KB/step off the LDS crossbar).
template <int CSZ>
__global__ void __launch_bounds__(512, 1)
lstm_split_kernel(const float* __restrict__ w_hh,
                  const int* __restrict__ sA, const int* __restrict__ sB,
                  const float* __restrict__ emb, const float* __restrict__ w_ih,
                  const float* __restrict__ b_ih, const float* __restrict__ b_hh,
                  int wait_tiles, int n_worker_ctas)
{
    extern __shared__ float smf[];

    if (blockIdx.x >= 4 * CSZ) {
        worker_body(blockIdx.x - 4 * CSZ, n_worker_ctas, reinterpret_cast<char*>(smf),
                    sA, sB, emb, w_ih, b_ih, b_hh);
        return;
    }

    constexpr int NT   = 512;
    constexpr int NW   = 16;
    constexpr int UPC  = HH / CSZ;        // 32
    constexpr int ROWS = 4 * UPC;         // 128
    constexpr int RPW  = ROWS / NW;       // 8
    constexpr int REG_ROWS  = 3;
    constexpr int SMEM_ROWS = 5;
    constexpr int CHUNK = UPC * 4;        // 128 B
    constexpr uint32_t TX_TOTAL = HH * 4; // 2048 B

    float* w_sm  = smf;                                     // NW*SMEM_ROWS*HH
    float* h_s   = w_sm + NW * SMEM_ROWS * HH;              // [2][HH] parity
    float* gates = h_s + 2 * HH;                            // [ROWS]
    float* stage = gates + ROWS;                            // [2][UPC]
    unsigned long long* s_bar = reinterpret_cast<unsigned long long*>(stage + 2 * UPC);

    const int tid  = threadIdx.x;
    const int lane = tid & 31;
    const int wid  = tid >> 5;
    const int cl   = blockIdx.x / CSZ;    // 0..3
    const int dir  = cl >> 1;
    const int sent = cl & 1;
    const int rank = blockIdx.x % CSZ;
    const int ku   = rank * UPC;

    for (int i = tid; i < 2 * HH; i += NT) h_s[i] = 0.f;
    if (tid == 0) {
        MBAR_INIT(smem_u32(&s_bar[0]), 1);
        MBAR_INIT(smem_u32(&s_bar[1]), 1);
    }

    const float* wbase = w_hh + (size_t)dir * 2048 * HH;
    const int r_first = wid * RPW;
    const float* wrow0 = wbase + ((size_t)(r_first / UPC) * HH + ku + (r_first % UPC)) * HH;

    for (int j = 0; j < SMEM_ROWS; ++j) {
        const float4* src = reinterpret_cast<const float4*>(wrow0 + (size_t)(REG_ROWS + j) * HH);
        float4* dst = reinterpret_cast<float4*>(w_sm + (size_t)(wid * SMEM_ROWS + j) * HH);
        for (int i = lane; i < HH / 4; i += 32) dst[i] = src[i];
    }

    ulonglong2 wreg[REG_ROWS][4];
#pragma unroll
    for (int j = 0; j < REG_ROWS; ++j) {
        const ulonglong2* wr = reinterpret_cast<const ulonglong2*>(wrow0 + (size_t)j * HH);
#pragma unroll
        for (int i = 0; i < 4; ++i) wreg[j][i] = wr[lane + 32 * i];
    }

    __syncthreads();
    asm volatile("barrier.cluster.arrive.aligned;" ::: "memory");
    asm volatile("barrier.cluster.wait.aligned;"   ::: "memory");

    const uint32_t bar_a[2]  = { smem_u32(&s_bar[0]), smem_u32(&s_bar[1]) };
    const uint32_t hbuf_a[2] = { smem_u32(h_s), smem_u32(h_s + HH) };
    const uint32_t stage_a   = smem_u32(stage);

    const ulonglong2* wsm2 = reinterpret_cast<const ulonglong2*>(
        w_sm + (size_t)(wid * SMEM_ROWS) * HH);

    float c_st = 0.f;   // warp 0, lane = unit

    for (int t = 0; t < TT; ++t) {
        const int rb = t & 1;
        const int wb = (t + 1) & 1;
        const int bi = t & 1;
        const int ph = (t >> 1) & 1;
        const int sb = t & 1;

        if (wait_tiles && (t & 63) == 0) {
            const int* c0 = &g_tile_cnt[dir * 2 + sent][t >> 6];
            while (ld_acq_gpu(c0) < 32) {}
        }

        if (tid == 0) MBAR_EXPECT_TX(bar_a[bi], TX_TOTAL);

        float gxv[4];
        if (wid == 0) {
            const float* px = g_gx + ((size_t)(dir * 2 + sent) * TT + t) * 2048 + ku + lane;
#pragma unroll
            for (int g = 0; g < 4; ++g) gxv[g] = __ldg(px + g * HH);
        }

        const ulonglong2* h2 = reinterpret_cast<const ulonglong2*>(h_s + rb * HH);
        ulonglong2 ha[4];
#pragma unroll
        for (int i = 0; i < 4; ++i) ha[i] = h2[lane + 32 * i];

        unsigned long long a8[RPW];
#pragma unroll
        for (int j = 0; j < RPW; ++j) a8[j] = 0ull;
#pragma unroll
        for (int j = 0; j < RPW; ++j) {
            ulonglong2 wv0, wv1, wv2, wv3;
            if (j < REG_ROWS) {
                wv0 = wreg[j][0]; wv1 = wreg[j][1]; wv2 = wreg[j][2]; wv3 = wreg[j][3];
            } else {
                const ulonglong2* wr = wsm2 + (size_t)(j - REG_ROWS) * (HH / 4);
                wv0 = wr[lane]; wv1 = wr[lane + 32]; wv2 = wr[lane + 64]; wv3 = wr[lane + 96];
            }
            fma2(a8[j], wv0.x, ha[0].x); fma2(a8[j], wv0.y, ha[0].y);
            fma2(a8[j], wv1.x, ha[1].x); fma2(a8[j], wv1.y, ha[1].y);
            fma2(a8[j], wv2.x, ha[2].x); fma2(a8[j], wv2.y, ha[2].y);
            fma2(a8[j], wv3.x, ha[3].x); fma2(a8[j], wv3.y, ha[3].y);
        }
        float s8[RPW];
#pragma unroll
        for (int j = 0; j < RPW; ++j) s8[j] = acc2_sum(a8[j]);
        reduce4_store_rows(pack2(s8[0], s8[4]), pack2(s8[1], s8[5]),
                           pack2(s8[2], s8[6]), pack2(s8[3], s8[7]),
                           gates, r_first, lane);

        __syncthreads();   // gates complete

        if (wid == 0) {
            const int u = lane;
            float g0 = gates[0 * UPC + u] + gxv[0];
            float g1 = gates[1 * UPC + u] + gxv[1];
            float g2 = gates[2 * UPC + u] + gxv[2];
            float g3 = gates[3 * UPC + u] + gxv[3];
            c_st = sigf(g1) * c_st + sigf(g0) * tanh_hw(g2);
            float hv = sigf(g3) * tanh_hw(c_st);
            stage[sb * UPC + u] = hv;
            if (t == TT - 1) g_h[0][dir][sent][ku + u] = hv;
            __syncwarp();
            asm volatile("fence.proxy.async.shared::cta;" ::: "memory");
            if (lane < CSZ) {
                uint32_t src  = stage_a + (sb * UPC) * 4;
                uint32_t ldst = hbuf_a[wb] + ku * 4;
                uint32_t rdst = mapa_u32(ldst, (uint32_t)lane);
                uint32_t rbar = mapa_u32(bar_a[bi], (uint32_t)lane);
                asm volatile(
                    "cp.async.bulk.shared::cluster.shared::cta.mbarrier::complete_tx::bytes "
                    "[%0], [%1], %2, [%3];"
                    :: "r"(rdst), "r"(src), "n"(CHUNK), "r"(rbar) : "memory");
            }
        }

        MBAR_WAIT_PARITY(bar_a[bi], (uint32_t)ph);
    }
}

// ---------------- combined fused kernel (fallback) ----------------------------------
template <int CSZ>
__global__ void __launch_bounds__(512, 1)
lstm_fused_kernel(const float* __restrict__ w_hh,
                  const int* __restrict__ sA, const int* __restrict__ sB,
                  const float* __restrict__ emb, const float* __restrict__ w_ih,
                  const float* __restrict__ b_ih, const float* __restrict__ b_hh,
                  int wait_tiles, int n_worker_ctas)
{
    extern __shared__ float smf[];

    if (blockIdx.x >= 2 * CSZ) {
        worker_body(blockIdx.x - 2 * CSZ, n_worker_ctas, reinterpret_cast<char*>(smf),
                    sA, sB, emb, w_ih, b_ih, b_hh);
        return;
    }

    constexpr int NT   = 512;
    constexpr int NW   = 16;
    constexpr int UPC  = HH / CSZ;
    constexpr int ROWS = 4 * UPC;
    constexpr int RPW  = ROWS / NW;
    constexpr int REG_ROWS  = 2;
    constexpr int SMEM_ROWS = 6;
    constexpr int UIT  = UPC / 32;
    constexpr int CHUNK = UPC * 4;
    constexpr uint32_t TX_TOTAL = 2 * HH * 4;

    float* w_sm  = smf;
    float* h_s   = w_sm + NW * SMEM_ROWS * HH;
    float* gates = h_s + 4 * HH;
    float* stage = gates + 2 * ROWS;
    unsigned long long* s_bar = reinterpret_cast<unsigned long long*>(stage + 4 * UPC);

    const int tid  = threadIdx.x;
    const int lane = tid & 31;
    const int wid  = tid >> 5;
    const int dir  = blockIdx.x / CSZ;
    const int rank = blockIdx.x % CSZ;
    const int ku   = rank * UPC;

    for (int i = tid; i < 2 * HH; i += NT) h_s[i] = 0.f;
    if (tid == 0) {
        MBAR_INIT(smem_u32(&s_bar[0]), 1);
        MBAR_INIT(smem_u32(&s_bar[1]), 1);
    }

    const float* wbase = w_hh + (size_t)dir * 2048 * HH;
    const int r_first = wid * RPW;
    const float* wrow0 = wbase + ((size_t)(r_first / UPC) * HH + ku + (r_first % UPC)) * HH;

    for (int j = 0; j < SMEM_ROWS; ++j) {
        const float4* src = reinterpret_cast<const float4*>(wrow0 + (size_t)(REG_ROWS + j) * HH);
        float4* dst = reinterpret_cast<float4*>(w_sm + (size_t)(wid * SMEM_ROWS + j) * HH);
        for (int i = lane; i < HH / 4; i += 32) dst[i] = src[i];
    }

    ulonglong2 wreg[REG_ROWS][4];
#pragma unroll
    for (int j = 0; j < REG_ROWS; ++j) {
        const ulonglong2* wr = reinterpret_cast<const ulonglong2*>(wrow0 + (size_t)j * HH);
#pragma unroll
        for (int i = 0; i < 4; ++i) wreg[j][i] = wr[lane + 32 * i];
    }

    __syncthreads();
    asm volatile("barrier.cluster.arrive.aligned;" ::: "memory");
    asm volatile("barrier.cluster.wait.aligned;"   ::: "memory");

    const uint32_t bar_a[2]  = { smem_u32(&s_bar[0]), smem_u32(&s_bar[1]) };
    const uint32_t hbuf_a[2] = { smem_u32(h_s), smem_u32(h_s + 2 * HH) };
    const uint32_t stage_a   = smem_u32(stage);

    const ulonglong2* wsm2 = reinterpret_cast<const ulonglong2*>(
        w_sm + (size_t)(wid * SMEM_ROWS) * HH);

    float c_st[UIT];
#pragma unroll
    for (int i = 0; i < UIT; ++i) c_st[i] = 0.f;

    for (int t = 0; t < TT; ++t) {
        const int rb = t & 1;
        const int wb = (t + 1) & 1;
        const int bi = t & 1;
        const int ph = (t >> 1) & 1;

        if (wait_tiles && (t & 63) == 0) {
            const int tt = t >> 6;
            const int* c0 = &g_tile_cnt[dir * 2 + 0][tt];
            const int* c1 = &g_tile_cnt[dir * 2 + 1][tt];
            while (ld_acq_gpu(c0) < 32) {}
            while (ld_acq_gpu(c1) < 32) {}
        }

        if (tid == 0) MBAR_EXPECT_TX(bar_a[bi], TX_TOTAL);

        float gxv[UIT][4];
        if (wid < 2) {
            const float* px = g_gx + ((size_t)(dir * 2 + wid) * TT + t) * 2048 + ku;
#pragma unroll
            for (int it = 0; it < UIT; ++it) {
                int u = lane + 32 * it;
#pragma unroll
                for (int g = 0; g < 4; ++g) gxv[it][g] = __ldg(px + g * HH + u);
            }
        }

        const ulonglong2* hA2 = reinterpret_cast<const ulonglong2*>(h_s + rb * 2 * HH);
        const ulonglong2* hB2 = reinterpret_cast<const ulonglong2*>(h_s + rb * 2 * HH + HH);
        ulonglong2 ha[4], hb[4];
#pragma unroll
        for (int i = 0; i < 4; ++i) {
            ha[i] = hA2[lane + 32 * i];
            hb[i] = hB2[lane + 32 * i];
        }

#pragma unroll
        for (int b = 0; b < RPW / 4; ++b) {
            unsigned long long aA[4] = {0,0,0,0}, aB[4] = {0,0,0,0};
#pragma unroll
            for (int r = 0; r < 4; ++r) {
                const int j = 4 * b + r;
                ulonglong2 wv0, wv1, wv2, wv3;
                if (j < REG_ROWS) {
                    wv0 = wreg[j][0]; wv1 = wreg[j][1]; wv2 = wreg[j][2]; wv3 = wreg[j][3];
                } else {
                    const ulonglong2* wr = wsm2 + (size_t)(j - REG_ROWS) * (HH / 4);
                    wv0 = wr[lane]; wv1 = wr[lane + 32]; wv2 = wr[lane + 64]; wv3 = wr[lane + 96];
                }
                fma2(aA[r], wv0.x, ha[0].x); fma2(aA[r], wv0.y, ha[0].y);
                fma2(aA[r], wv1.x, ha[1].x); fma2(aA[r], wv1.y, ha[1].y);
                fma2(aA[r], wv2.x, ha[2].x); fma2(aA[r], wv2.y, ha[2].y);
                fma2(aA[r], wv3.x, ha[3].x); fma2(aA[r], wv3.y, ha[3].y);
                fma2(aB[r], wv0.x, hb[0].x); fma2(aB[r], wv0.y, hb[0].y);
                fma2(aB[r], wv1.x, hb[1].x); fma2(aB[r], wv1.y, hb[1].y);
                fma2(aB[r], wv2.x, hb[2].x); fma2(aB[r], wv2.y, hb[2].y);
                fma2(aB[r], wv3.x, hb[3].x); fma2(aB[r], wv3.y, hb[3].y);
            }
            reduce4_store(pack2(acc2_sum(aA[0]), acc2_sum(aB[0])),
                          pack2(acc2_sum(aA[1]), acc2_sum(aB[1])),
                          pack2(acc2_sum(aA[2]), acc2_sum(aB[2])),
                          pack2(acc2_sum(aA[3]), acc2_sum(aB[3])),
                          gates, ROWS, r_first + 4 * b, lane);
        }

        __syncthreads();

        if (wid < 2) {
            const int sb = t & 1;
            float* stg = stage + sb * 2 * UPC + wid * UPC;
#pragma unroll
            for (int it = 0; it < UIT; ++it) {
                int u = lane + 32 * it;
                float g0 = gates[wid * ROWS + 0 * UPC + u] + gxv[it][0];
                float g1 = gates[wid * ROWS + 1 * UPC + u] + gxv[it][1];
                float g2 = gates[wid * ROWS + 2 * UPC + u] + gxv[it][2];
                float g3 = gates[wid * ROWS + 3 * UPC + u] + gxv[it][3];
                c_st[it] = sigf(g1) * c_st[it] + sigf(g0) * tanh_hw(g2);
                float hv = sigf(g3) * tanh_hw(c_st[it]);
                stg[u] = hv;
                if (t == TT - 1) g_h[0][dir][wid][ku + u] = hv;
            }
            __syncwarp();
            asm volatile("fence.proxy.async.shared::cta;" ::: "memory");
            if (lane < CSZ) {
                uint32_t src  = stage_a + ((t & 1) * 2 * UPC + wid * UPC) * 4;
                uint32_t ldst = hbuf_a[wb] + (wid * HH + ku) * 4;
                uint32_t rdst = mapa_u32(ldst, (uint32_t)lane);
                uint32_t rbar = mapa_u32(bar_a[bi], (uint32_t)lane);
                asm volatile(
                    "cp.async.bulk.shared::cluster.shared::cta.mbarrier::complete_tx::bytes "
                    "[%0], [%1], %2, [%3];"
                    :: "r"(rdst), "r"(src), "n"(CHUNK), "r"(rbar) : "memory");
            }
        }

        MBAR_WAIT_PARITY(bar_a[bi], (uint32_t)ph);
    }
}

// ---------------- phase 3: head ------------------------------------------------------
__global__ void head_kernel(const float* __restrict__ bi_w, const float* __restrict__ bi_b,
                            const float* __restrict__ blA, const float* __restrict__ blB,
                            const float* __restrict__ bl_b,
                            const float* __restrict__ out_w, const float* __restrict__ out_b,
                            float* __restrict__ out)
{
    __shared__ float hA[HH], hB[HH];
    __shared__ float red[16];
    const int j = threadIdx.x;
    const float w0 = bi_w[0], w1 = bi_w[1], bb = bi_b[0];

    hA[j] = w0 * g_h[0][0][0][j] + w1 * g_h[0][1][0][j] + bb;
    hB[j] = w0 * g_h[0][0][1][j] + w1 * g_h[0][1][1][j] + bb;
    __syncthreads();

    float acc = bl_b[j];
#pragma unroll 4
    for (int i = 0; i < HH; ++i)
        acc += hA[i] * blA[(size_t)i * HH + j] + hB[i] * blB[(size_t)i * HH + j];

    float v = tanhf(acc) * out_w[j];
#pragma unroll
    for (int off = 16; off; off >>= 1) v += __shfl_xor_sync(0xffffffffu, v, off);
    if ((j & 31) == 0) red[j >> 5] = v;
    __syncthreads();
    if (j < 16) {
        float r = red[j];
#pragma unroll
        for (int off = 8; off; off >>= 1) r += __shfl_xor_sync(0x0000ffffu, r, off);
        if (j == 0) out[0] = 1.f / (1.f + expf(-(r + out_b[0])));
    }
}

// ---------------- launch --------------------------------------------------------------
extern "C" void kernel_launch(void* const* d_in, const int* in_sizes, int n_in,
                              void* d_out, int out_size)
{
    (void)in_sizes; (void)n_in; (void)out_size;
    const int*   sentA = (const int*)d_in[0];
    const int*   sentB = (const int*)d_in[1];
    const float* emb   = (const float*)d_in[3];
    const float* w_ih  = (const float*)d_in[4];
    const float* w_hh  = (const float*)d_in[5];
    const float* b_ih  = (const float*)d_in[6];
    const float* b_hh  = (const float*)d_in[7];
    const float* bi_w  = (const float*)d_in[8];
    const float* bi_b  = (const float*)d_in[9];
    const float* blA   = (const float*)d_in[10];
    const float* blB   = (const float*)d_in[11];
    const float* bl_b  = (const float*)d_in[12];
    const float* out_w = (const float*)d_in[13];
    const float* out_b = (const float*)d_in[14];
    float* out = (float*)d_out;

    const int smem_split = (int)((16 * 5 * HH + 2 * HH + 4 * (HH / 16) + 2 * (HH / 16) + 128) * sizeof(float)) + 16;
    const int smem_comb  = (int)((16 * 6 * HH + 4 * HH + 2 * 4 * (HH / 16) + 4 * (HH / 16)) * sizeof(float)) + 16;

    cudaFuncSetAttribute(lstm_split_kernel<16>,
                         cudaFuncAttributeNonPortableClusterSizeAllowed, 1);
    cudaFuncSetAttribute(lstm_split_kernel<16>,
                         cudaFuncAttributeMaxDynamicSharedMemorySize, smem_split);
    cudaFuncSetAttribute(lstm_fused_kernel<16>,
                         cudaFuncAttributeNonPortableClusterSizeAllowed, 1);
    cudaFuncSetAttribute(lstm_fused_kernel<16>,
                         cudaFuncAttributeMaxDynamicSharedMemorySize, smem_comb);

    cudaLaunchConfig_t cfg = {};
    cfg.blockDim = dim3(512, 1, 1);
    cfg.stream = 0;
    cudaLaunchAttribute attr[1];
    attr[0].id = cudaLaunchAttributeClusterDimension;
    attr[0].val.clusterDim.x = 16; attr[0].val.clusterDim.y = 1; attr[0].val.clusterDim.z = 1;
    cfg.attrs = attr;
    cfg.numAttrs = 1;

    cfg.gridDim = dim3(4 * 16, 1, 1);
    cfg.dynamicSmemBytes = smem_split;
    int ncl_split = 0;
    cudaError_t es = cudaOccupancyMaxActiveClusters(&ncl_split, lstm_split_kernel<16>, &cfg);
    if (es != cudaSuccess) { ncl_split = 0; (void)cudaGetLastError(); }

    if (ncl_split >= 5) {
        int use = ncl_split < 9 ? ncl_split : 9;
        int nworkers = (use - 4) * 16;
        cfg.gridDim = dim3(use * 16, 1, 1);
        cfg.dynamicSmemBytes = smem_split;
        init_kernel<<<1, 128>>>();
        cudaLaunchKernelEx(&cfg, lstm_split_kernel<16>,
                           w_hh, sentA, sentB, emb, w_ih, b_ih, b_hh, 1, nworkers);
    } else if (ncl_split == 4) {
        gemm_gx_kernel<<<dim3(32, 64, 2), 256>>>(sentA, sentB, emb, w_ih, b_ih, b_hh);
        cfg.gridDim = dim3(4 * 16, 1, 1);
        cfg.dynamicSmemBytes = smem_split;
        cudaLaunchKernelEx(&cfg, lstm_split_kernel<16>,
                           w_hh, sentA, sentB, emb, w_ih, b_ih, b_hh, 0, 0);
    } else {
        cfg.gridDim = dim3(2 * 16, 1, 1);
        cfg.dynamicSmemBytes = smem_comb;
        int ncl = 0;
        cudaError_t e = cudaOccupancyMaxActiveClusters(&ncl, lstm_fused_kernel<16>, &cfg);
        if (e == cudaSuccess && ncl >= 3) {
            int use = ncl < 9 ? ncl : 9;
            int nworkers = (use - 2) * 16;
            cfg.gridDim = dim3(use * 16, 1, 1);
            init_kernel<<<1, 128>>>();
            cudaLaunchKernelEx(&cfg, lstm_fused_kernel<16>,
                               w_hh, sentA, sentB, emb, w_ih, b_ih, b_hh, 1, nworkers);
        } else {
            (void)cudaGetLastError();
            gemm_gx_kernel<<<dim3(32, 64, 2), 256>>>(sentA, sentB, emb, w_ih, b_ih, b_hh);
            cfg.gridDim = dim3(2 * 16, 1, 1);
            cudaLaunchKernelEx(&cfg, lstm_fused_kernel<16>,
                               w_hh, sentA, sentB, emb, w_ih, b_ih, b_hh, 0, 0);
        }
    }

    head_kernel<<<1, 512>>>(bi_w, bi_b, blA, blB, bl_b, out_w, out_b, out);
}